// round 9
// baseline (speedup 1.0000x reference)
#include <cuda_runtime.h>
#include <cuda_bf16.h>
#include <math.h>
#include <stdint.h>

#define BSZ  8
#define SLEN 100
#define GG   800
#define NNODE 200
#define NEDGE 600
#define DD   128
#define DCC  64
#define HHID 256
#define CP1N 111
#define FEATN 177
#define GN   160000

// ---------------- scratch globals -------------------------------------------
__device__ float g_x[(size_t)GN * DD];
__device__ __nv_bfloat16 g_xhi[(size_t)GN * DD];
__device__ __nv_bfloat16 g_xlo[(size_t)GN * DD];
__device__ __nv_bfloat16 g_agghi[(size_t)GN * DD];
__device__ __nv_bfloat16 g_agglo[(size_t)GN * DD];
__device__ __nv_bfloat16 g_CombT_hi[4 * 384 * 128];   // [l][j][k]
__device__ __nv_bfloat16 g_Whh_hi[384 * 128];         // [j][k]
__device__ __nv_bfloat16 g_Td_hi[64 * 128];           // [c][k]
__device__ float g_ggnn[(size_t)GN * DCC];
__device__ float g_attn[GG * DCC];
__device__ float g_mean8[8];
__device__ float g_LihT[FEATN * 1024];
__device__ float g_WhhP[256 * 1024];
__device__ float g_pre[(size_t)GG * 1024];
__device__ float g_hout[(size_t)GG * HHID];
__device__ float g_fp[GG];
__device__ float g_bce[GG];
__device__ float g_mf[GG];
// CSR scratch (layer-invariant)
__device__ int   g_csr_src[GG * NEDGE];
__device__ float g_csr_w[GG * NEDGE];
__device__ int   g_csr_ofs[GG * (NNODE + 1)];

__device__ __forceinline__ float sigmoidf_(float v) { return 1.f / (1.f + expf(-v)); }
__device__ __forceinline__ float tanh_fast(float x) {
    float y; asm("tanh.approx.f32 %0, %1;" : "=f"(y) : "f"(x)); return y;
}
__device__ __forceinline__ float sigmoid_fast(float x) {
    return fmaf(tanh_fast(0.5f * x), 0.5f, 0.5f);
}

__device__ __forceinline__ void cvt_hilo(float v, __nv_bfloat16& h, __nv_bfloat16& l) {
    h = __float2bfloat16_rn(v);
    l = __float2bfloat16_rn(v - __bfloat162float(h));
}

__device__ __forceinline__ uint32_t smem_u32(const void* p) {
    uint32_t a;
    asm("{ .reg .u64 t; cvta.to.shared.u64 t, %1; cvt.u32.u64 %0, t; }" : "=r"(a) : "l"(p));
    return a;
}
__device__ __forceinline__ void ldsm_x4(uint32_t& a0, uint32_t& a1, uint32_t& a2,
                                        uint32_t& a3, uint32_t addr) {
    asm volatile("ldmatrix.sync.aligned.m8n8.x4.shared.b16 {%0,%1,%2,%3}, [%4];"
                 : "=r"(a0), "=r"(a1), "=r"(a2), "=r"(a3) : "r"(addr));
}
__device__ __forceinline__ void mma16816(float* d, uint32_t a0, uint32_t a1, uint32_t a2,
                                         uint32_t a3, uint32_t b0, uint32_t b1) {
    asm volatile("mma.sync.aligned.m16n8k16.row.col.f32.bf16.bf16.f32 "
                 "{%0,%1,%2,%3}, {%4,%5,%6,%7}, {%8,%9}, {%0,%1,%2,%3};"
                 : "+f"(d[0]), "+f"(d[1]), "+f"(d[2]), "+f"(d[3])
                 : "r"(a0), "r"(a1), "r"(a2), "r"(a3), "r"(b0), "r"(b1));
}
__device__ __forceinline__ void cp_async16(uint32_t saddr, const void* gaddr) {
    asm volatile("cp.async.cg.shared.global [%0], [%1], 16;" :: "r"(saddr), "l"(gaddr));
}
#define CP_COMMIT() asm volatile("cp.async.commit_group;" ::: "memory")
#define CP_WAIT(n)  asm volatile("cp.async.wait_group %0;" :: "n"(n) : "memory")
#define CLUSTER_BAR() do { \
    asm volatile("barrier.cluster.arrive.aligned;" ::: "memory"); \
    asm volatile("barrier.cluster.wait.aligned;" ::: "memory"); \
} while (0)

// ---------------- prep -------------------------------------------------------
__global__ void prep_kernel(const float* __restrict__ edge_embed_w,
                            const float* __restrict__ gru_w_hh,
                            const float* __restrict__ transdim_w,
                            const float* __restrict__ lstm_w_ih,
                            const float* __restrict__ lstm_w_hh) {
    const int T3 = 64 * 128, T4 = FEATN * 1024, T5 = 256 * 1024, T6 = 384 * 128;
    int total = 8 + T3 + T4 + T5 + T6;
    for (int i = blockIdx.x * blockDim.x + threadIdx.x; i < total;
         i += gridDim.x * blockDim.x) {
        int t = i;
        if (t < 8) {
            float s = 0.f;
            for (int d = 0; d < DD; d++) s += edge_embed_w[t * DD + d];
            g_mean8[t] = s / (float)DD;
            continue;
        }
        t -= 8;
        if (t < T3) { g_Td_hi[t] = __float2bfloat16_rn(transdim_w[t]); continue; }
        t -= T3;
        if (t < T4) {
            int k = t / 1024, p = t % 1024; int q = p & 3, j = p >> 2;
            g_LihT[t] = lstm_w_ih[(q * 256 + j) * FEATN + k];
            continue;
        }
        t -= T4;
        if (t < T5) {
            int k = t / 1024, p = t % 1024; int q = p & 3, j = p >> 2;
            g_WhhP[t] = lstm_w_hh[(q * 256 + j) * 256 + k];
            continue;
        }
        t -= T5;
        g_Whh_hi[t] = __float2bfloat16_rn(gru_w_hh[t]);
    }
}

// CombT[l][j][k] = sum_d W_l[k,d] * W_ih[j,d]
__global__ void comb_kernel(const float* __restrict__ ggnn_w,
                            const float* __restrict__ gru_w_ih) {
    int t = blockIdx.x * blockDim.x + threadIdx.x;
    if (t >= 4 * 384 * 128) return;
    int l = t / (384 * 128); int r = t % (384 * 128);
    int j = r / 128, k = r % 128;
    const float4* wl = (const float4*)(ggnn_w + ((size_t)l * 128 + k) * 128);
    const float4* wi = (const float4*)(gru_w_ih + (size_t)j * 128);
    float s = 0.f;
#pragma unroll 8
    for (int d = 0; d < 32; d++) {
        float4 a = wl[d], b = wi[d];
        s += a.x * b.x + a.y * b.y + a.z * b.z + a.w * b.w;
    }
    g_CombT_hi[t] = __float2bfloat16_rn(s);
}

// ---------------- gather -----------------------------------------------------
__global__ void gather_kernel(const int* __restrict__ node_id,
                              const float* __restrict__ embed) {
    int warp = threadIdx.x >> 5, lane = threadIdx.x & 31;
    int row = blockIdx.x * 8 + warp;
    if (row >= GN) return;
    int nid = node_id[row];
    float4 v = *(const float4*)&embed[(size_t)nid * DD + lane * 4];
    size_t o = (size_t)row * DD + lane * 4;
    *(float4*)&g_x[o] = v;
    __nv_bfloat16 h0, l0, h1, l1, h2, l2, h3, l3;
    cvt_hilo(v.x, h0, l0); cvt_hilo(v.y, h1, l1);
    cvt_hilo(v.z, h2, l2); cvt_hilo(v.w, h3, l3);
    ((__nv_bfloat162*)&g_xhi[o])[0] = __nv_bfloat162(h0, h1);
    ((__nv_bfloat162*)&g_xhi[o])[1] = __nv_bfloat162(h2, h3);
    ((__nv_bfloat162*)&g_xlo[o])[0] = __nv_bfloat162(l0, l1);
    ((__nv_bfloat162*)&g_xlo[o])[1] = __nv_bfloat162(l2, l3);
}

// ---------------- CSR build (once; layer-invariant) --------------------------
__global__ void csr_build(const int* __restrict__ edge,
                          const int* __restrict__ edge_type) {
    __shared__ int s_src[NEDGE];
    __shared__ int s_dst[NEDGE];
    __shared__ int cnt[NNODE + 1];
    __shared__ int ofs[NNODE + 1];
    __shared__ float sm8[8];
    int g = blockIdx.x;
    int tid = threadIdx.x;
    const int* eg = edge + (size_t)g * 2 * NEDGE;
    if (tid < 8) sm8[tid] = g_mean8[tid];
    for (int e = tid; e < NEDGE; e += 256) { s_src[e] = eg[e]; s_dst[e] = eg[NEDGE + e]; }
    for (int i = tid; i <= NNODE; i += 256) cnt[i] = 0;
    __syncthreads();
    for (int e = tid; e < NEDGE; e += 256) atomicAdd(&cnt[s_dst[e]], 1);
    __syncthreads();
    if (tid == 0) {
        int acc = 0;
        for (int n = 0; n <= NNODE; n++) { int c = cnt[n]; ofs[n] = acc; acc += c; }
    }
    __syncthreads();
    for (int i = tid; i <= NNODE; i += 256) g_csr_ofs[g * (NNODE + 1) + i] = ofs[i];
    for (int i = tid; i < NNODE; i += 256) cnt[i] = ofs[i];
    __syncthreads();
    for (int e = tid; e < NEDGE; e += 256) {
        int p = atomicAdd(&cnt[s_dst[e]], 1);
        g_csr_src[g * NEDGE + p] = s_src[e];
        g_csr_w[g * NEDGE + p] = sm8[edge_type[(size_t)g * NEDGE + e]];
    }
}

// ---------------- per-layer edge scatter: smem x tile + prebuilt CSR ---------
__global__ void __launch_bounds__(512, 2) scatter_csr(int dummy) {
    extern __shared__ float sx[];
    int g = blockIdx.x;
    int tid = threadIdx.x;
    {
        const float4* xg4 = (const float4*)(g_x + (size_t)g * NNODE * DD);
        float4* sx4 = (float4*)sx;
        for (int i = tid; i < NNODE * DD / 4; i += 512) sx4[i] = xg4[i];
    }
    __syncthreads();
    int warp = tid >> 5, lane = tid & 31;
    const int* ofs = g_csr_ofs + g * (NNODE + 1);
    const int* srcv = g_csr_src + g * NEDGE;
    const float* wv = g_csr_w + g * NEDGE;
    for (int n = warp; n < NNODE; n += 16) {
        float4 acc = make_float4(0.f, 0.f, 0.f, 0.f);
        int s0 = ofs[n], s1 = ofs[n + 1];
        for (int i = s0; i < s1; i++) {
            int src = srcv[i];
            float w = wv[i];
            float4 v = *(const float4*)&sx[src * DD + lane * 4];
            acc.x += w * v.x; acc.y += w * v.y; acc.z += w * v.z; acc.w += w * v.w;
        }
        size_t o = ((size_t)(g * NNODE + n)) * DD + lane * 4;
        __nv_bfloat16 h0, l0, h1, l1, h2, l2, h3, l3;
        cvt_hilo(acc.x, h0, l0); cvt_hilo(acc.y, h1, l1);
        cvt_hilo(acc.z, h2, l2); cvt_hilo(acc.w, h3, l3);
        ((__nv_bfloat162*)&g_agghi[o])[0] = __nv_bfloat162(h0, h1);
        ((__nv_bfloat162*)&g_agghi[o])[1] = __nv_bfloat162(h2, h3);
        ((__nv_bfloat162*)&g_agglo[o])[0] = __nv_bfloat162(l0, l1);
        ((__nv_bfloat162*)&g_agglo[o])[1] = __nv_bfloat162(l2, l3);
    }
    (void)dummy;
}

// ---------------- fused HMMA GGNN layer: 2-pass (A hi/lo x B hi) -------------
#define SMA_AGH 0
#define SMA_AGL 16384
#define SMA_XH  32768
#define SMA_XL  49152
#define SMB0    65536
#define SMB1    98304
#define SMB_BIA 131072
#define SM_TOT  (131072 + 2048)

__global__ void __launch_bounds__(256, 1) layer_mma(int layer,
                                                    const float* __restrict__ b_ih,
                                                    const float* __restrict__ b_hh) {
    extern __shared__ __align__(128) char smx[];
    uint32_t sbase = smem_u32(smx);
    int tid = threadIdx.x, wid = tid >> 5, lane = tid & 31;
    int rowBase = blockIdx.x * 64;
    int rg = wid >> 1;
    int cg = wid & 1;
    float* sb = (float*)(smx + SMB_BIA);
    if (tid < 128) {
        sb[tid]       = b_ih[tid] + b_hh[tid];
        sb[128 + tid] = b_ih[128 + tid] + b_hh[128 + tid];
        sb[256 + tid] = b_ih[256 + tid];
        sb[384 + tid] = b_hh[256 + tid];
    }
    {
        const __nv_bfloat16* s0 = g_agghi + (size_t)rowBase * 128;
        const __nv_bfloat16* s1 = g_agglo + (size_t)rowBase * 128;
        const __nv_bfloat16* s2 = g_xhi + (size_t)rowBase * 128;
        const __nv_bfloat16* s3 = g_xlo + (size_t)rowBase * 128;
#pragma unroll
        for (int q = 0; q < 4; q++) {
            int i = tid + 256 * q;
            int r = i >> 4, c = i & 15;
            uint32_t off = r * 256 + ((c ^ (r & 7)) << 4);
            cp_async16(sbase + SMA_AGH + off, s0 + i * 8);
            cp_async16(sbase + SMA_AGL + off, s1 + i * 8);
            cp_async16(sbase + SMA_XH + off, s2 + i * 8);
            cp_async16(sbase + SMA_XL + off, s3 + i * 8);
        }
    }
    auto load_b = [&](int c) {
        int j0 = (c >> 1) * 128;
        bool isComb = !(c & 1);
        const __nv_bfloat16* bh = isComb ? (g_CombT_hi + ((size_t)layer * 384 + j0) * 128)
                                         : (g_Whh_hi + (size_t)j0 * 128);
        uint32_t dst = sbase + ((c & 1) ? SMB1 : SMB0);
#pragma unroll
        for (int q = 0; q < 8; q++) {
            int i = tid + 256 * q;
            int r = i >> 4, cc = i & 15;
            uint32_t off = r * 256 + ((cc ^ (r & 7)) << 4);
            cp_async16(dst + off, bh + i * 8);
        }
    };
    load_b(0);
    CP_COMMIT();

    float acc[4][8][4];
#pragma unroll
    for (int b = 0; b < 4; b++)
#pragma unroll
        for (int n = 0; n < 8; n++)
#pragma unroll
            for (int e = 0; e < 4; e++) acc[b][n][e] = 0.f;

    const int a_r = rg * 16 + (lane & 15);
    const int a_kh = lane >> 4;
    const int b_grp = lane >> 3;
    const int b_nt_off = b_grp >> 1;
    const int b_kh = b_grp & 1;
    const int b_nl = lane & 7;

#pragma unroll
    for (int chunk = 0; chunk < 6; chunk++) {
        if (chunk < 5) { load_b(chunk + 1); CP_COMMIT(); }
        if (chunk < 5) { CP_WAIT(1); } else { CP_WAIT(0); }
        __syncthreads();
        const bool isComb = !(chunk & 1);
        const int bank = (chunk < 2) ? 0 : (chunk < 4) ? 1 : (chunk == 4) ? 2 : 3;
        const uint32_t bufH = sbase + ((chunk & 1) ? SMB1 : SMB0);
        const uint32_t aHi = sbase + (isComb ? SMA_AGH : SMA_XH);
        const uint32_t aLo = sbase + (isComb ? SMA_AGL : SMA_XL);
        for (int ks = 0; ks < 8; ks++) {
            uint32_t ach = (uint32_t)(((ks * 2 + a_kh) ^ (a_r & 7)) << 4) + a_r * 256;
            uint32_t ah0, ah1, ah2, ah3, al0, al1, al2, al3;
            ldsm_x4(ah0, ah1, ah2, ah3, aHi + ach);
            ldsm_x4(al0, al1, al2, al3, aLo + ach);
#pragma unroll
            for (int nt2 = 0; nt2 < 8; nt2 += 2) {
                int n = cg * 64 + (nt2 + b_nt_off) * 8 + b_nl;
                uint32_t boff = (uint32_t)n * 256 + (uint32_t)(((ks * 2 + b_kh) ^ (n & 7)) << 4);
                uint32_t bh0, bh1, bh2, bh3;
                ldsm_x4(bh0, bh1, bh2, bh3, bufH + boff);
                mma16816(acc[bank][nt2], ah0, ah1, ah2, ah3, bh0, bh1);
                mma16816(acc[bank][nt2], al0, al1, al2, al3, bh0, bh1);
                mma16816(acc[bank][nt2 + 1], ah0, ah1, ah2, ah3, bh2, bh3);
                mma16816(acc[bank][nt2 + 1], al0, al1, al2, al3, bh2, bh3);
            }
        }
        __syncthreads();
    }

    int tq = lane >> 2, tr = lane & 3;
#pragma unroll
    for (int nt = 0; nt < 8; nt++) {
        int j = cg * 64 + nt * 8 + tr * 2;
#pragma unroll
        for (int h = 0; h < 2; h++) {
            int m = rowBase + rg * 16 + tq + h * 8;
            float r0 = sigmoid_fast(acc[0][nt][2 * h] + sb[j]);
            float r1 = sigmoid_fast(acc[0][nt][2 * h + 1] + sb[j + 1]);
            float z0 = sigmoid_fast(acc[1][nt][2 * h] + sb[128 + j]);
            float z1 = sigmoid_fast(acc[1][nt][2 * h + 1] + sb[128 + j + 1]);
            float n0 = tanh_fast(acc[2][nt][2 * h] + sb[256 + j] +
                             r0 * (acc[3][nt][2 * h] + sb[384 + j]));
            float n1 = tanh_fast(acc[2][nt][2 * h + 1] + sb[256 + j + 1] +
                             r1 * (acc[3][nt][2 * h + 1] + sb[384 + j + 1]));
            size_t o = (size_t)m * 128 + j;
            float2 xo = *(const float2*)&g_x[o];
            float xn0 = (1.f - z0) * n0 + z0 * xo.x;
            float xn1 = (1.f - z1) * n1 + z1 * xo.y;
            *(float2*)&g_x[o] = make_float2(xn0, xn1);
            __nv_bfloat16 h0, l0, h1, l1;
            cvt_hilo(xn0, h0, l0); cvt_hilo(xn1, h1, l1);
            *(__nv_bfloat162*)&g_xhi[o] = __nv_bfloat162(h0, h1);
            *(__nv_bfloat162*)&g_xlo[o] = __nv_bfloat162(l0, l1);
        }
    }
}

// ---------------- transdim GEMM via HMMA (2-pass) -----------------------------
#define TD_AH 0
#define TD_AL 32768
#define TD_BH 65536
#define TD_TOT 81920
__global__ void __launch_bounds__(256, 2) gemm_td() {
    extern __shared__ __align__(128) char smt[];
    uint32_t sbase = smem_u32(smt);
    int tid = threadIdx.x, wid = tid >> 5, lane = tid & 31;
    int rowBase = blockIdx.x * 128;
    {
        const __nv_bfloat16* s2 = g_xhi + (size_t)rowBase * 128;
        const __nv_bfloat16* s3 = g_xlo + (size_t)rowBase * 128;
#pragma unroll
        for (int q = 0; q < 8; q++) {
            int i = tid + 256 * q;
            int r = i >> 4, c = i & 15;
            uint32_t off = r * 256 + ((c ^ (r & 7)) << 4);
            cp_async16(sbase + TD_AH + off, s2 + i * 8);
            cp_async16(sbase + TD_AL + off, s3 + i * 8);
        }
    }
    {
#pragma unroll
        for (int q = 0; q < 4; q++) {
            int i = tid + 256 * q;
            int r = i >> 4, c = i & 15;
            uint32_t off = r * 256 + ((c ^ (r & 7)) << 4);
            cp_async16(sbase + TD_BH + off, g_Td_hi + i * 8);
        }
    }
    CP_COMMIT();
    CP_WAIT(0);
    __syncthreads();

    float acc[8][4];
#pragma unroll
    for (int n = 0; n < 8; n++)
#pragma unroll
        for (int e = 0; e < 4; e++) acc[n][e] = 0.f;

    const int a_r = wid * 16 + (lane & 15);
    const int a_kh = lane >> 4;
    const int b_grp = lane >> 3;
    const int b_nt_off = b_grp >> 1;
    const int b_kh = b_grp & 1;
    const int b_nl = lane & 7;

    for (int ks = 0; ks < 8; ks++) {
        uint32_t ach = (uint32_t)(((ks * 2 + a_kh) ^ (a_r & 7)) << 4) + a_r * 256;
        uint32_t ah0, ah1, ah2, ah3, al0, al1, al2, al3;
        ldsm_x4(ah0, ah1, ah2, ah3, sbase + TD_AH + ach);
        ldsm_x4(al0, al1, al2, al3, sbase + TD_AL + ach);
#pragma unroll
        for (int nt2 = 0; nt2 < 8; nt2 += 2) {
            int n = (nt2 + b_nt_off) * 8 + b_nl;
            uint32_t boff = (uint32_t)n * 256 + (uint32_t)(((ks * 2 + b_kh) ^ (n & 7)) << 4);
            uint32_t bh0, bh1, bh2, bh3;
            ldsm_x4(bh0, bh1, bh2, bh3, sbase + TD_BH + boff);
            mma16816(acc[nt2], ah0, ah1, ah2, ah3, bh0, bh1);
            mma16816(acc[nt2], al0, al1, al2, al3, bh0, bh1);
            mma16816(acc[nt2 + 1], ah0, ah1, ah2, ah3, bh2, bh3);
            mma16816(acc[nt2 + 1], al0, al1, al2, al3, bh2, bh3);
        }
    }
    int tq = lane >> 2, tr = lane & 3;
#pragma unroll
    for (int nt = 0; nt < 8; nt++) {
        int j = nt * 8 + tr * 2;
#pragma unroll
        for (int h = 0; h < 2; h++) {
            int m = rowBase + wid * 16 + tq + h * 8;
            *(float2*)&g_ggnn[(size_t)m * DCC + j] =
                make_float2(acc[nt][2 * h], acc[nt][2 * h + 1]);
        }
    }
}

// ---------------- attention (collapsed node weights) --------------------------
__global__ void attn_kernel(const float* __restrict__ c_id,
                            const float* __restrict__ c_embed,
                            const float* __restrict__ concept_embedding) {
    extern __shared__ float smf[];
    float* shg = smf;
    float* pbuf = shg + NNODE * 65;
    float* qbuf = pbuf + 8 * NNODE;
    float* wnode = qbuf + 8 * 64;
    float* accd = wnode + NNODE;
    float* snum = accd + 64;
    int g = blockIdx.x;
    int tid = threadIdx.x;
    for (int i = tid; i < NNODE * DCC; i += 256) {
        int n = i >> 6, d = i & 63;
        shg[n * 65 + d] = g_ggnn[(size_t)(g * NNODE + n) * DCC + d];
    }
    for (int i = tid; i < NNODE; i += 256) wnode[i] = 0.f;
    if (tid < 64) accd[tid] = 0.f;
    if (tid == 0) snum[0] = 0.f;
    __syncthreads();
    if (tid < CP1N) atomicAdd(snum, c_id[g * CP1N + tid]);
    __syncthreads();
    int warp = tid >> 5, lane = tid & 31;
    for (int c = warp; c < CP1N; c += 8) {
        float ce = c_embed[g * CP1N + c];
        if (ce == 0.f) continue;
        qbuf[warp * 64 + lane] = ce * concept_embedding[c * DCC + lane];
        qbuf[warp * 64 + lane + 32] = ce * concept_embedding[c * DCC + lane + 32];
        __syncwarp();
        float mx = -1e30f;
        for (int n = lane; n < NNODE; n += 32) {
            float s = 0.f;
#pragma unroll 16
            for (int d = 0; d < DCC; d++) s += qbuf[warp * 64 + d] * shg[n * 65 + d];
            pbuf[warp * NNODE + n] = s;
            mx = fmaxf(mx, s);
        }
#pragma unroll
        for (int o = 16; o > 0; o >>= 1) mx = fmaxf(mx, __shfl_xor_sync(0xffffffffu, mx, o));
        float ssum = 0.f;
        for (int n = lane; n < NNODE; n += 32) {
            float p = expf(pbuf[warp * NNODE + n] - mx);
            pbuf[warp * NNODE + n] = p;
            ssum += p;
        }
#pragma unroll
        for (int o = 16; o > 0; o >>= 1) ssum += __shfl_xor_sync(0xffffffffu, ssum, o);
        float inv = ce / ssum;
        for (int n = lane; n < NNODE; n += 32)
            atomicAdd(&wnode[n], inv * pbuf[warp * NNODE + n]);
    }
    __syncthreads();
    {
        int d = tid & 63, q = tid >> 6;
        float partial = 0.f;
        for (int n = q * 50; n < q * 50 + 50; n++)
            partial += wnode[n] * shg[n * 65 + d];
        atomicAdd(&accd[d], partial);
    }
    __syncthreads();
    if (tid < DCC) {
        float nv = snum[0];
        if (nv == 0.f) nv = 1.f;
        g_attn[g * DCC + tid] = accd[tid] / nv;
    }
}

// ---------------- LSTM input GEMM: 8 sequences per block ---------------------
__global__ void lstm_pre_kernel(const float* __restrict__ c_embed,
                                const float* __restrict__ cur_result,
                                const float* __restrict__ lstm_b_ih) {
    __shared__ float xin[8][FEATN];
    int s0 = blockIdx.x * 8;
    int tid = threadIdx.x;
    for (int i = tid; i < 8 * FEATN; i += 256) {
        int si = i / FEATN, f = i % FEATN;
        int s = s0 + si;
        float v;
        if (f < CP1N) v = c_embed[(size_t)s * CP1N + f];
        else if (f < CP1N + DCC) v = g_attn[(size_t)s * DCC + (f - CP1N)];
        else v = cur_result[(size_t)s * 2 + (f - CP1N - DCC)];
        xin[si][f] = v;
    }
    __syncthreads();
    int m = blockIdx.y * 256 + tid;
    int q = m & 3, j = m >> 2;
    float b = lstm_b_ih[q * 256 + j];
    float a0 = b, a1 = b, a2 = b, a3 = b, a4 = b, a5 = b, a6 = b, a7 = b;
    for (int k = 0; k < FEATN; k++) {
        float w = g_LihT[(size_t)k * 1024 + m];
        a0 += xin[0][k] * w; a1 += xin[1][k] * w;
        a2 += xin[2][k] * w; a3 += xin[3][k] * w;
        a4 += xin[4][k] * w; a5 += xin[5][k] * w;
        a6 += xin[6][k] * w; a7 += xin[7][k] * w;
    }
    g_pre[(size_t)(s0 + 0) * 1024 + m] = a0;
    g_pre[(size_t)(s0 + 1) * 1024 + m] = a1;
    g_pre[(size_t)(s0 + 2) * 1024 + m] = a2;
    g_pre[(size_t)(s0 + 3) * 1024 + m] = a3;
    g_pre[(size_t)(s0 + 4) * 1024 + m] = a4;
    g_pre[(size_t)(s0 + 5) * 1024 + m] = a5;
    g_pre[(size_t)(s0 + 6) * 1024 + m] = a6;
    g_pre[(size_t)(s0 + 7) * 1024 + m] = a7;
}

// LSTM recurrence: cluster of 8 CTAs per batch element; double-buffered h,
// ONE cluster barrier per step.
__global__ void __cluster_dims__(8, 1, 1) __launch_bounds__(128, 1)
lstm_rec_kernel(const float* __restrict__ b_hh) {
    extern __shared__ float sml[];
    float* sW = sml;
    float* sh = sml + 256 * 128;
    int tid = threadIdx.x;
    int r = blockIdx.x & 7;
    int b = blockIdx.x >> 3;
    for (int i = tid; i < 256 * 128; i += 128)
        sW[i] = g_WhhP[(size_t)(i >> 7) * 1024 + r * 128 + (i & 127)];
    for (int i = tid; i < 512; i += 128) sh[i] = 0.f;
    int q = tid & 3, jl = tid >> 2;
    int jg = r * 32 + jl;
    float bias = b_hh[q * 256 + jg];
    float c = 0.f;
    uint32_t sh_my0 = smem_u32(&sh[jg]);
    uint32_t sh_my1 = smem_u32(&sh[256 + jg]);
    __syncthreads();
    CLUSTER_BAR();
    int lbase = (tid & 31) & ~3;
    for (int t = 0; t < SLEN; t++) {
        int s = b * SLEN + t;
        const float* shc = sh + 256 * (t & 1);
        uint32_t sh_next = (t & 1) ? sh_my0 : sh_my1;
        float acc = g_pre[(size_t)s * 1024 + r * 128 + tid] + bias;
#pragma unroll 8
        for (int k = 0; k < 256; k++) acc += shc[k] * sW[k * 128 + tid];
        float vi = __shfl_sync(0xffffffffu, acc, lbase + 0);
        float vf = __shfl_sync(0xffffffffu, acc, lbase + 1);
        float vg = __shfl_sync(0xffffffffu, acc, lbase + 2);
        float vo = __shfl_sync(0xffffffffu, acc, lbase + 3);
        if (q == 0) {
            c = sigmoid_fast(vf) * c + sigmoid_fast(vi) * tanh_fast(vg);
            float h = sigmoid_fast(vo) * tanh_fast(c);
            g_hout[(size_t)s * HHID + jg] = h;
#pragma unroll
            for (int dst = 0; dst < 8; dst++) {
                uint32_t rem;
                asm("mapa.shared::cluster.u32 %0, %1, %2;" : "=r"(rem)
                    : "r"(sh_next), "r"(dst));
                asm volatile("st.shared::cluster.f32 [%0], %1;" :: "r"(rem), "f"(h)
                             : "memory");
            }
        }
        CLUSTER_BAR();
    }
}

// ---------------- pred + BCE + final -----------------------------------------
__global__ void pred_kernel(const float* __restrict__ target_c,
                            const float* __restrict__ result,
                            const float* __restrict__ pred_w,
                            const float* __restrict__ pred_b) {
    __shared__ float sh[HHID];
    __shared__ float s_p, s_n;
    int i = blockIdx.x, tid = threadIdx.x;
    sh[tid] = g_hout[(size_t)i * HHID + tid];
    sh[tid + 128] = g_hout[(size_t)i * HHID + tid + 128];
    if (tid == 0) { s_p = 0.f; s_n = 0.f; }
    __syncthreads();
    int warp = tid >> 5, lane = tid & 31;
    float lp = 0.f, ln = 0.f;
    for (int c = warp; c < CP1N; c += 4) {
        float tc = target_c[i * CP1N + c];
        if (tc != 0.f) {
            float s = 0.f;
            for (int d = lane; d < HHID; d += 32) s += pred_w[c * HHID + d] * sh[d];
#pragma unroll
            for (int o = 16; o > 0; o >>= 1) s += __shfl_xor_sync(0xffffffffu, s, o);
            if (lane == 0) { lp += tc * (s + pred_b[c]); ln += tc; }
        }
    }
    if (lane == 0) { atomicAdd(&s_p, lp); atomicAdd(&s_n, ln); }
    __syncthreads();
    if (tid == 0) {
        float nc = s_n;
        int mask = nc > 0.f;
        float fp = s_p / (mask ? nc : 1.f);
        float ft = result[i];
        float bce = fmaxf(fp, 0.f) - fp * ft + log1pf(expf(-fabsf(fp)));
        g_fp[i] = fp;
        g_mf[i] = mask ? 1.f : 0.f;
        g_bce[i] = mask ? bce : 0.f;
    }
}

__global__ void final_kernel(const float* __restrict__ result, float* __restrict__ out,
                             int out_size) {
    __shared__ float rb[256], rm[256];
    int tid = threadIdx.x;
    float sb = 0.f, smm = 0.f;
    for (int i = tid; i < GG; i += 256) { sb += g_bce[i]; smm += g_mf[i]; }
    rb[tid] = sb; rm[tid] = smm;
    __syncthreads();
    for (int o = 128; o > 0; o >>= 1) {
        if (tid < o) { rb[tid] += rb[tid + o]; rm[tid] += rm[tid + o]; }
        __syncthreads();
    }
    if (tid == 0 && out_size > 0) out[0] = rb[0] / fmaxf(rm[0], 1.f);
    for (int i = tid; i < GG; i += 256) {
        if (1 + i < out_size) out[1 + i] = 1.f / (1.f + expf(-g_fp[i]));
        if (1 + GG + i < out_size) out[1 + GG + i] = result[i];
    }
}

// ---------------- launcher ---------------------------------------------------
extern "C" void kernel_launch(void* const* d_in, const int* in_sizes, int n_in,
                              void* d_out, int out_size) {
    const float* c_id       = (const float*)d_in[1];
    const int*   node_id    = (const int*)d_in[2];
    const int*   edge       = (const int*)d_in[3];
    const int*   edge_type  = (const int*)d_in[4];
    const float* target_c   = (const float*)d_in[5];
    const float* result     = (const float*)d_in[6];
    const float* c_embed    = (const float*)d_in[7];
    const float* cur_result = (const float*)d_in[8];
    const float* node_embed_w = (const float*)d_in[9];
    const float* edge_embed_w = (const float*)d_in[10];
    const float* ggnn_w     = (const float*)d_in[11];
    const float* gru_w_ih   = (const float*)d_in[12];
    const float* gru_w_hh   = (const float*)d_in[13];
    const float* gru_b_ih   = (const float*)d_in[14];
    const float* gru_b_hh   = (const float*)d_in[15];
    const float* transdim_w = (const float*)d_in[16];
    const float* concept_embedding = (const float*)d_in[17];
    const float* lstm_w_ih  = (const float*)d_in[18];
    const float* lstm_w_hh  = (const float*)d_in[19];
    const float* lstm_b_ih  = (const float*)d_in[20];
    const float* lstm_b_hh  = (const float*)d_in[21];
    const float* pred_w     = (const float*)d_in[22];
    const float* pred_b     = (const float*)d_in[23];
    float* out = (float*)d_out;
    (void)in_sizes; (void)n_in;

    const int SCAT_SMEM = NNODE * DD * 4;
    const int LSTM_SMEM = 256 * 128 * 4 + 512 * 4;
    const int ATTN_SMEM = (NNODE * 65 + 8 * NNODE + 8 * 64 + NNODE + 64 + 4) * 4;
    cudaFuncSetAttribute(layer_mma, cudaFuncAttributeMaxDynamicSharedMemorySize, SM_TOT);
    cudaFuncSetAttribute(gemm_td, cudaFuncAttributeMaxDynamicSharedMemorySize, TD_TOT);
    cudaFuncSetAttribute(attn_kernel, cudaFuncAttributeMaxDynamicSharedMemorySize, ATTN_SMEM);
    cudaFuncSetAttribute(scatter_csr, cudaFuncAttributeMaxDynamicSharedMemorySize, SCAT_SMEM);
    cudaFuncSetAttribute(lstm_rec_kernel, cudaFuncAttributeMaxDynamicSharedMemorySize,
                         LSTM_SMEM);

    prep_kernel<<<1960, 256>>>(edge_embed_w, gru_w_hh, transdim_w, lstm_w_ih, lstm_w_hh);
    comb_kernel<<<(4 * 384 * 128 + 255) / 256, 256>>>(ggnn_w, gru_w_ih);
    gather_kernel<<<GN / 8, 256>>>(node_id, node_embed_w);
    csr_build<<<GG, 256>>>(edge, edge_type);

    for (int l = 0; l < 4; l++) {
        scatter_csr<<<GG, 512, SCAT_SMEM>>>(0);
        layer_mma<<<GN / 64, 256, SM_TOT>>>(l, gru_b_ih, gru_b_hh);
    }

    gemm_td<<<GN / 128, 256, TD_TOT>>>();
    attn_kernel<<<GG, 256, ATTN_SMEM>>>(c_id, c_embed, concept_embedding);
    lstm_pre_kernel<<<dim3(GG / 8, 4), 256>>>(c_embed, cur_result, lstm_b_ih);
    lstm_rec_kernel<<<BSZ * 8, 128, LSTM_SMEM>>>(lstm_b_hh);
    pred_kernel<<<GG, 128>>>(target_c, result, pred_w, pred_b);
    final_kernel<<<1, 256>>>(result, out, out_size);
}

// round 10
// speedup vs baseline: 1.4100x; 1.4100x over previous
#include <cuda_runtime.h>
#include <cuda_bf16.h>
#include <math.h>
#include <stdint.h>

#define BSZ  8
#define SLEN 100
#define GG   800
#define NNODE 200
#define NEDGE 600
#define DD   128
#define DCC  64
#define HHID 256
#define CP1N 111
#define FEATN 177
#define GN   160000

// ---------------- scratch globals -------------------------------------------
__device__ float g_x[(size_t)GN * DD];
__device__ __nv_bfloat16 g_xhi[(size_t)GN * DD];
__device__ __nv_bfloat16 g_xlo[(size_t)GN * DD];
__device__ __nv_bfloat16 g_agghi[(size_t)GN * DD];
__device__ __nv_bfloat16 g_agglo[(size_t)GN * DD];
__device__ __nv_bfloat16 g_CombT_hi[4 * 384 * 128];   // [l][j][k]
__device__ __nv_bfloat16 g_Whh_hi[384 * 128];         // [j][k]
__device__ __nv_bfloat16 g_Td_hi[64 * 128];           // [c][k]
__device__ float g_ggnn[(size_t)GN * DCC];
__device__ float g_attn[GG * DCC];
__device__ float g_mean8[8];
__device__ float g_LihT[FEATN * 1024];
__device__ float g_WhhP[256 * 1024];
__device__ float g_pre[(size_t)GG * 1024];
__device__ float g_hout[(size_t)GG * HHID];
__device__ float g_fp[GG];
__device__ float g_bce[GG];
__device__ float g_mf[GG];
// CSR scratch (layer-invariant)
__device__ int   g_csr_src[GG * NEDGE];
__device__ float g_csr_w[GG * NEDGE];
__device__ int   g_csr_ofs[GG * (NNODE + 1)];

__device__ __forceinline__ float sigmoidf_(float v) { return 1.f / (1.f + expf(-v)); }
__device__ __forceinline__ float tanh_fast(float x) {
    float y; asm("tanh.approx.f32 %0, %1;" : "=f"(y) : "f"(x)); return y;
}
__device__ __forceinline__ float sigmoid_fast(float x) {
    return fmaf(tanh_fast(0.5f * x), 0.5f, 0.5f);
}

__device__ __forceinline__ void cvt_hilo(float v, __nv_bfloat16& h, __nv_bfloat16& l) {
    h = __float2bfloat16_rn(v);
    l = __float2bfloat16_rn(v - __bfloat162float(h));
}

__device__ __forceinline__ uint32_t smem_u32(const void* p) {
    uint32_t a;
    asm("{ .reg .u64 t; cvta.to.shared.u64 t, %1; cvt.u32.u64 %0, t; }" : "=r"(a) : "l"(p));
    return a;
}
__device__ __forceinline__ void ldsm_x4(uint32_t& a0, uint32_t& a1, uint32_t& a2,
                                        uint32_t& a3, uint32_t addr) {
    asm volatile("ldmatrix.sync.aligned.m8n8.x4.shared.b16 {%0,%1,%2,%3}, [%4];"
                 : "=r"(a0), "=r"(a1), "=r"(a2), "=r"(a3) : "r"(addr));
}
__device__ __forceinline__ void mma16816(float* d, uint32_t a0, uint32_t a1, uint32_t a2,
                                         uint32_t a3, uint32_t b0, uint32_t b1) {
    asm volatile("mma.sync.aligned.m16n8k16.row.col.f32.bf16.bf16.f32 "
                 "{%0,%1,%2,%3}, {%4,%5,%6,%7}, {%8,%9}, {%0,%1,%2,%3};"
                 : "+f"(d[0]), "+f"(d[1]), "+f"(d[2]), "+f"(d[3])
                 : "r"(a0), "r"(a1), "r"(a2), "r"(a3), "r"(b0), "r"(b1));
}
__device__ __forceinline__ void cp_async16(uint32_t saddr, const void* gaddr) {
    asm volatile("cp.async.cg.shared.global [%0], [%1], 16;" :: "r"(saddr), "l"(gaddr));
}
#define CP_COMMIT() asm volatile("cp.async.commit_group;" ::: "memory")
#define CP_WAIT(n)  asm volatile("cp.async.wait_group %0;" :: "n"(n) : "memory")
#define CLUSTER_BAR() do { \
    asm volatile("barrier.cluster.arrive.aligned;" ::: "memory"); \
    asm volatile("barrier.cluster.wait.aligned;" ::: "memory"); \
} while (0)

// ---------------- prep -------------------------------------------------------
__global__ void prep_kernel(const float* __restrict__ edge_embed_w,
                            const float* __restrict__ gru_w_hh,
                            const float* __restrict__ transdim_w,
                            const float* __restrict__ lstm_w_ih,
                            const float* __restrict__ lstm_w_hh) {
    const int T3 = 64 * 128, T4 = FEATN * 1024, T5 = 256 * 1024, T6 = 384 * 128;
    int total = 8 + T3 + T4 + T5 + T6;
    for (int i = blockIdx.x * blockDim.x + threadIdx.x; i < total;
         i += gridDim.x * blockDim.x) {
        int t = i;
        if (t < 8) {
            float s = 0.f;
            for (int d = 0; d < DD; d++) s += edge_embed_w[t * DD + d];
            g_mean8[t] = s / (float)DD;
            continue;
        }
        t -= 8;
        if (t < T3) { g_Td_hi[t] = __float2bfloat16_rn(transdim_w[t]); continue; }
        t -= T3;
        if (t < T4) {
            int k = t / 1024, p = t % 1024; int q = p & 3, j = p >> 2;
            g_LihT[t] = lstm_w_ih[(q * 256 + j) * FEATN + k];
            continue;
        }
        t -= T4;
        if (t < T5) {
            int k = t / 1024, p = t % 1024; int q = p & 3, j = p >> 2;
            g_WhhP[t] = lstm_w_hh[(q * 256 + j) * 256 + k];
            continue;
        }
        t -= T5;
        g_Whh_hi[t] = __float2bfloat16_rn(gru_w_hh[t]);
    }
}

// CombT[l][j][k] = sum_d W_l[k,d] * W_ih[j,d]
__global__ void comb_kernel(const float* __restrict__ ggnn_w,
                            const float* __restrict__ gru_w_ih) {
    int t = blockIdx.x * blockDim.x + threadIdx.x;
    if (t >= 4 * 384 * 128) return;
    int l = t / (384 * 128); int r = t % (384 * 128);
    int j = r / 128, k = r % 128;
    const float4* wl = (const float4*)(ggnn_w + ((size_t)l * 128 + k) * 128);
    const float4* wi = (const float4*)(gru_w_ih + (size_t)j * 128);
    float s = 0.f;
#pragma unroll 8
    for (int d = 0; d < 32; d++) {
        float4 a = wl[d], b = wi[d];
        s += a.x * b.x + a.y * b.y + a.z * b.z + a.w * b.w;
    }
    g_CombT_hi[t] = __float2bfloat16_rn(s);
}

// ---------------- gather -----------------------------------------------------
__global__ void gather_kernel(const int* __restrict__ node_id,
                              const float* __restrict__ embed) {
    int warp = threadIdx.x >> 5, lane = threadIdx.x & 31;
    int row = blockIdx.x * 8 + warp;
    if (row >= GN) return;
    int nid = node_id[row];
    float4 v = *(const float4*)&embed[(size_t)nid * DD + lane * 4];
    size_t o = (size_t)row * DD + lane * 4;
    *(float4*)&g_x[o] = v;
    __nv_bfloat16 h0, l0, h1, l1, h2, l2, h3, l3;
    cvt_hilo(v.x, h0, l0); cvt_hilo(v.y, h1, l1);
    cvt_hilo(v.z, h2, l2); cvt_hilo(v.w, h3, l3);
    ((__nv_bfloat162*)&g_xhi[o])[0] = __nv_bfloat162(h0, h1);
    ((__nv_bfloat162*)&g_xhi[o])[1] = __nv_bfloat162(h2, h3);
    ((__nv_bfloat162*)&g_xlo[o])[0] = __nv_bfloat162(l0, l1);
    ((__nv_bfloat162*)&g_xlo[o])[1] = __nv_bfloat162(l2, l3);
}

// ---------------- CSR build (once; layer-invariant) --------------------------
__global__ void csr_build(const int* __restrict__ edge,
                          const int* __restrict__ edge_type) {
    __shared__ int s_src[NEDGE];
    __shared__ int s_dst[NEDGE];
    __shared__ int cnt[NNODE + 1];
    __shared__ int ofs[NNODE + 1];
    __shared__ float sm8[8];
    int g = blockIdx.x;
    int tid = threadIdx.x;
    const int* eg = edge + (size_t)g * 2 * NEDGE;
    if (tid < 8) sm8[tid] = g_mean8[tid];
    for (int e = tid; e < NEDGE; e += 256) { s_src[e] = eg[e]; s_dst[e] = eg[NEDGE + e]; }
    for (int i = tid; i <= NNODE; i += 256) cnt[i] = 0;
    __syncthreads();
    for (int e = tid; e < NEDGE; e += 256) atomicAdd(&cnt[s_dst[e]], 1);
    __syncthreads();
    if (tid == 0) {
        int acc = 0;
        for (int n = 0; n <= NNODE; n++) { int c = cnt[n]; ofs[n] = acc; acc += c; }
    }
    __syncthreads();
    for (int i = tid; i <= NNODE; i += 256) g_csr_ofs[g * (NNODE + 1) + i] = ofs[i];
    for (int i = tid; i < NNODE; i += 256) cnt[i] = ofs[i];
    __syncthreads();
    for (int e = tid; e < NEDGE; e += 256) {
        int p = atomicAdd(&cnt[s_dst[e]], 1);
        g_csr_src[g * NEDGE + p] = s_src[e];
        g_csr_w[g * NEDGE + p] = sm8[edge_type[(size_t)g * NEDGE + e]];
    }
}

// ---------------- per-layer edge scatter: smem x tile + prebuilt CSR ---------
__global__ void __launch_bounds__(512, 2) scatter_csr(int dummy) {
    extern __shared__ float sx[];
    int g = blockIdx.x;
    int tid = threadIdx.x;
    {
        const float4* xg4 = (const float4*)(g_x + (size_t)g * NNODE * DD);
        float4* sx4 = (float4*)sx;
        for (int i = tid; i < NNODE * DD / 4; i += 512) sx4[i] = xg4[i];
    }
    __syncthreads();
    int warp = tid >> 5, lane = tid & 31;
    const int* ofs = g_csr_ofs + g * (NNODE + 1);
    const int* srcv = g_csr_src + g * NEDGE;
    const float* wv = g_csr_w + g * NEDGE;
    for (int n = warp; n < NNODE; n += 16) {
        float4 acc = make_float4(0.f, 0.f, 0.f, 0.f);
        int s0 = ofs[n], s1 = ofs[n + 1];
        for (int i = s0; i < s1; i++) {
            int src = srcv[i];
            float w = wv[i];
            float4 v = *(const float4*)&sx[src * DD + lane * 4];
            acc.x += w * v.x; acc.y += w * v.y; acc.z += w * v.z; acc.w += w * v.w;
        }
        size_t o = ((size_t)(g * NNODE + n)) * DD + lane * 4;
        __nv_bfloat16 h0, l0, h1, l1, h2, l2, h3, l3;
        cvt_hilo(acc.x, h0, l0); cvt_hilo(acc.y, h1, l1);
        cvt_hilo(acc.z, h2, l2); cvt_hilo(acc.w, h3, l3);
        ((__nv_bfloat162*)&g_agghi[o])[0] = __nv_bfloat162(h0, h1);
        ((__nv_bfloat162*)&g_agghi[o])[1] = __nv_bfloat162(h2, h3);
        ((__nv_bfloat162*)&g_agglo[o])[0] = __nv_bfloat162(l0, l1);
        ((__nv_bfloat162*)&g_agglo[o])[1] = __nv_bfloat162(l2, l3);
    }
    (void)dummy;
}

// ---------------- fused HMMA GGNN layer: 2-pass (A hi/lo x B hi) -------------
#define SMA_AGH 0
#define SMA_AGL 16384
#define SMA_XH  32768
#define SMA_XL  49152
#define SMB0    65536
#define SMB1    98304
#define SMB_BIA 131072
#define SM_TOT  (131072 + 2048)

__global__ void __launch_bounds__(256, 1) layer_mma(int layer,
                                                    const float* __restrict__ b_ih,
                                                    const float* __restrict__ b_hh) {
    extern __shared__ __align__(128) char smx[];
    uint32_t sbase = smem_u32(smx);
    int tid = threadIdx.x, wid = tid >> 5, lane = tid & 31;
    int rowBase = blockIdx.x * 64;
    int rg = wid >> 1;
    int cg = wid & 1;
    float* sb = (float*)(smx + SMB_BIA);
    if (tid < 128) {
        sb[tid]       = b_ih[tid] + b_hh[tid];
        sb[128 + tid] = b_ih[128 + tid] + b_hh[128 + tid];
        sb[256 + tid] = b_ih[256 + tid];
        sb[384 + tid] = b_hh[256 + tid];
    }
    {
        const __nv_bfloat16* s0 = g_agghi + (size_t)rowBase * 128;
        const __nv_bfloat16* s1 = g_agglo + (size_t)rowBase * 128;
        const __nv_bfloat16* s2 = g_xhi + (size_t)rowBase * 128;
        const __nv_bfloat16* s3 = g_xlo + (size_t)rowBase * 128;
#pragma unroll
        for (int q = 0; q < 4; q++) {
            int i = tid + 256 * q;
            int r = i >> 4, c = i & 15;
            uint32_t off = r * 256 + ((c ^ (r & 7)) << 4);
            cp_async16(sbase + SMA_AGH + off, s0 + i * 8);
            cp_async16(sbase + SMA_AGL + off, s1 + i * 8);
            cp_async16(sbase + SMA_XH + off, s2 + i * 8);
            cp_async16(sbase + SMA_XL + off, s3 + i * 8);
        }
    }
    auto load_b = [&](int c) {
        int j0 = (c >> 1) * 128;
        bool isComb = !(c & 1);
        const __nv_bfloat16* bh = isComb ? (g_CombT_hi + ((size_t)layer * 384 + j0) * 128)
                                         : (g_Whh_hi + (size_t)j0 * 128);
        uint32_t dst = sbase + ((c & 1) ? SMB1 : SMB0);
#pragma unroll
        for (int q = 0; q < 8; q++) {
            int i = tid + 256 * q;
            int r = i >> 4, cc = i & 15;
            uint32_t off = r * 256 + ((cc ^ (r & 7)) << 4);
            cp_async16(dst + off, bh + i * 8);
        }
    };
    load_b(0);
    CP_COMMIT();

    float acc[4][8][4];
#pragma unroll
    for (int b = 0; b < 4; b++)
#pragma unroll
        for (int n = 0; n < 8; n++)
#pragma unroll
            for (int e = 0; e < 4; e++) acc[b][n][e] = 0.f;

    const int a_r = rg * 16 + (lane & 15);
    const int a_kh = lane >> 4;
    const int b_grp = lane >> 3;
    const int b_nt_off = b_grp >> 1;
    const int b_kh = b_grp & 1;
    const int b_nl = lane & 7;

#pragma unroll
    for (int chunk = 0; chunk < 6; chunk++) {
        if (chunk < 5) { load_b(chunk + 1); CP_COMMIT(); }
        if (chunk < 5) { CP_WAIT(1); } else { CP_WAIT(0); }
        __syncthreads();
        const bool isComb = !(chunk & 1);
        const int bank = (chunk < 2) ? 0 : (chunk < 4) ? 1 : (chunk == 4) ? 2 : 3;
        const uint32_t bufH = sbase + ((chunk & 1) ? SMB1 : SMB0);
        const uint32_t aHi = sbase + (isComb ? SMA_AGH : SMA_XH);
        const uint32_t aLo = sbase + (isComb ? SMA_AGL : SMA_XL);
        for (int ks = 0; ks < 8; ks++) {
            uint32_t ach = (uint32_t)(((ks * 2 + a_kh) ^ (a_r & 7)) << 4) + a_r * 256;
            uint32_t ah0, ah1, ah2, ah3, al0, al1, al2, al3;
            ldsm_x4(ah0, ah1, ah2, ah3, aHi + ach);
            ldsm_x4(al0, al1, al2, al3, aLo + ach);
#pragma unroll
            for (int nt2 = 0; nt2 < 8; nt2 += 2) {
                int n = cg * 64 + (nt2 + b_nt_off) * 8 + b_nl;
                uint32_t boff = (uint32_t)n * 256 + (uint32_t)(((ks * 2 + b_kh) ^ (n & 7)) << 4);
                uint32_t bh0, bh1, bh2, bh3;
                ldsm_x4(bh0, bh1, bh2, bh3, bufH + boff);
                mma16816(acc[bank][nt2], ah0, ah1, ah2, ah3, bh0, bh1);
                mma16816(acc[bank][nt2], al0, al1, al2, al3, bh0, bh1);
                mma16816(acc[bank][nt2 + 1], ah0, ah1, ah2, ah3, bh2, bh3);
                mma16816(acc[bank][nt2 + 1], al0, al1, al2, al3, bh2, bh3);
            }
        }
        __syncthreads();
    }

    int tq = lane >> 2, tr = lane & 3;
#pragma unroll
    for (int nt = 0; nt < 8; nt++) {
        int j = cg * 64 + nt * 8 + tr * 2;
#pragma unroll
        for (int h = 0; h < 2; h++) {
            int m = rowBase + rg * 16 + tq + h * 8;
            float r0 = sigmoid_fast(acc[0][nt][2 * h] + sb[j]);
            float r1 = sigmoid_fast(acc[0][nt][2 * h + 1] + sb[j + 1]);
            float z0 = sigmoid_fast(acc[1][nt][2 * h] + sb[128 + j]);
            float z1 = sigmoid_fast(acc[1][nt][2 * h + 1] + sb[128 + j + 1]);
            float n0 = tanh_fast(acc[2][nt][2 * h] + sb[256 + j] +
                             r0 * (acc[3][nt][2 * h] + sb[384 + j]));
            float n1 = tanh_fast(acc[2][nt][2 * h + 1] + sb[256 + j + 1] +
                             r1 * (acc[3][nt][2 * h + 1] + sb[384 + j + 1]));
            size_t o = (size_t)m * 128 + j;
            float2 xo = *(const float2*)&g_x[o];
            float xn0 = fmaf(z0, xo.x - n0, n0);
            float xn1 = fmaf(z1, xo.y - n1, n1);
            *(float2*)&g_x[o] = make_float2(xn0, xn1);
            __nv_bfloat16 h0, l0, h1, l1;
            cvt_hilo(xn0, h0, l0); cvt_hilo(xn1, h1, l1);
            *(__nv_bfloat162*)&g_xhi[o] = __nv_bfloat162(h0, h1);
            *(__nv_bfloat162*)&g_xlo[o] = __nv_bfloat162(l0, l1);
        }
    }
}

// ---------------- transdim GEMM via HMMA (2-pass) -----------------------------
#define TD_AH 0
#define TD_AL 32768
#define TD_BH 65536
#define TD_TOT 81920
__global__ void __launch_bounds__(256, 2) gemm_td() {
    extern __shared__ __align__(128) char smt[];
    uint32_t sbase = smem_u32(smt);
    int tid = threadIdx.x, wid = tid >> 5, lane = tid & 31;
    int rowBase = blockIdx.x * 128;
    {
        const __nv_bfloat16* s2 = g_xhi + (size_t)rowBase * 128;
        const __nv_bfloat16* s3 = g_xlo + (size_t)rowBase * 128;
#pragma unroll
        for (int q = 0; q < 8; q++) {
            int i = tid + 256 * q;
            int r = i >> 4, c = i & 15;
            uint32_t off = r * 256 + ((c ^ (r & 7)) << 4);
            cp_async16(sbase + TD_AH + off, s2 + i * 8);
            cp_async16(sbase + TD_AL + off, s3 + i * 8);
        }
    }
    {
#pragma unroll
        for (int q = 0; q < 4; q++) {
            int i = tid + 256 * q;
            int r = i >> 4, c = i & 15;
            uint32_t off = r * 256 + ((c ^ (r & 7)) << 4);
            cp_async16(sbase + TD_BH + off, g_Td_hi + i * 8);
        }
    }
    CP_COMMIT();
    CP_WAIT(0);
    __syncthreads();

    float acc[8][4];
#pragma unroll
    for (int n = 0; n < 8; n++)
#pragma unroll
        for (int e = 0; e < 4; e++) acc[n][e] = 0.f;

    const int a_r = wid * 16 + (lane & 15);
    const int a_kh = lane >> 4;
    const int b_grp = lane >> 3;
    const int b_nt_off = b_grp >> 1;
    const int b_kh = b_grp & 1;
    const int b_nl = lane & 7;

    for (int ks = 0; ks < 8; ks++) {
        uint32_t ach = (uint32_t)(((ks * 2 + a_kh) ^ (a_r & 7)) << 4) + a_r * 256;
        uint32_t ah0, ah1, ah2, ah3, al0, al1, al2, al3;
        ldsm_x4(ah0, ah1, ah2, ah3, sbase + TD_AH + ach);
        ldsm_x4(al0, al1, al2, al3, sbase + TD_AL + ach);
#pragma unroll
        for (int nt2 = 0; nt2 < 8; nt2 += 2) {
            int n = (nt2 + b_nt_off) * 8 + b_nl;
            uint32_t boff = (uint32_t)n * 256 + (uint32_t)(((ks * 2 + b_kh) ^ (n & 7)) << 4);
            uint32_t bh0, bh1, bh2, bh3;
            ldsm_x4(bh0, bh1, bh2, bh3, sbase + TD_BH + boff);
            mma16816(acc[nt2], ah0, ah1, ah2, ah3, bh0, bh1);
            mma16816(acc[nt2], al0, al1, al2, al3, bh0, bh1);
            mma16816(acc[nt2 + 1], ah0, ah1, ah2, ah3, bh2, bh3);
            mma16816(acc[nt2 + 1], al0, al1, al2, al3, bh2, bh3);
        }
    }
    int tq = lane >> 2, tr = lane & 3;
#pragma unroll
    for (int nt = 0; nt < 8; nt++) {
        int j = nt * 8 + tr * 2;
#pragma unroll
        for (int h = 0; h < 2; h++) {
            int m = rowBase + wid * 16 + tq + h * 8;
            *(float2*)&g_ggnn[(size_t)m * DCC + j] =
                make_float2(acc[nt][2 * h], acc[nt][2 * h + 1]);
        }
    }
}

// ---------------- attention (collapsed node weights) --------------------------
__global__ void attn_kernel(const float* __restrict__ c_id,
                            const float* __restrict__ c_embed,
                            const float* __restrict__ concept_embedding) {
    extern __shared__ float smf[];
    float* shg = smf;
    float* pbuf = shg + NNODE * 65;
    float* qbuf = pbuf + 8 * NNODE;
    float* wnode = qbuf + 8 * 64;
    float* accd = wnode + NNODE;
    float* snum = accd + 64;
    int g = blockIdx.x;
    int tid = threadIdx.x;
    for (int i = tid; i < NNODE * DCC; i += 256) {
        int n = i >> 6, d = i & 63;
        shg[n * 65 + d] = g_ggnn[(size_t)(g * NNODE + n) * DCC + d];
    }
    for (int i = tid; i < NNODE; i += 256) wnode[i] = 0.f;
    if (tid < 64) accd[tid] = 0.f;
    if (tid == 0) snum[0] = 0.f;
    __syncthreads();
    if (tid < CP1N) atomicAdd(snum, c_id[g * CP1N + tid]);
    __syncthreads();
    int warp = tid >> 5, lane = tid & 31;
    for (int c = warp; c < CP1N; c += 8) {
        float ce = c_embed[g * CP1N + c];
        if (ce == 0.f) continue;
        qbuf[warp * 64 + lane] = ce * concept_embedding[c * DCC + lane];
        qbuf[warp * 64 + lane + 32] = ce * concept_embedding[c * DCC + lane + 32];
        __syncwarp();
        float mx = -1e30f;
        for (int n = lane; n < NNODE; n += 32) {
            float s = 0.f;
#pragma unroll 16
            for (int d = 0; d < DCC; d++) s += qbuf[warp * 64 + d] * shg[n * 65 + d];
            pbuf[warp * NNODE + n] = s;
            mx = fmaxf(mx, s);
        }
#pragma unroll
        for (int o = 16; o > 0; o >>= 1) mx = fmaxf(mx, __shfl_xor_sync(0xffffffffu, mx, o));
        float ssum = 0.f;
        for (int n = lane; n < NNODE; n += 32) {
            float p = expf(pbuf[warp * NNODE + n] - mx);
            pbuf[warp * NNODE + n] = p;
            ssum += p;
        }
#pragma unroll
        for (int o = 16; o > 0; o >>= 1) ssum += __shfl_xor_sync(0xffffffffu, ssum, o);
        float inv = ce / ssum;
        for (int n = lane; n < NNODE; n += 32)
            atomicAdd(&wnode[n], inv * pbuf[warp * NNODE + n]);
    }
    __syncthreads();
    {
        int d = tid & 63, q = tid >> 6;
        float partial = 0.f;
        for (int n = q * 50; n < q * 50 + 50; n++)
            partial += wnode[n] * shg[n * 65 + d];
        atomicAdd(&accd[d], partial);
    }
    __syncthreads();
    if (tid < DCC) {
        float nv = snum[0];
        if (nv == 0.f) nv = 1.f;
        g_attn[g * DCC + tid] = accd[tid] / nv;
    }
}

// ---------------- LSTM input GEMM: 8 sequences per block ---------------------
__global__ void lstm_pre_kernel(const float* __restrict__ c_embed,
                                const float* __restrict__ cur_result,
                                const float* __restrict__ lstm_b_ih) {
    __shared__ float xin[8][FEATN];
    int s0 = blockIdx.x * 8;
    int tid = threadIdx.x;
    for (int i = tid; i < 8 * FEATN; i += 256) {
        int si = i / FEATN, f = i % FEATN;
        int s = s0 + si;
        float v;
        if (f < CP1N) v = c_embed[(size_t)s * CP1N + f];
        else if (f < CP1N + DCC) v = g_attn[(size_t)s * DCC + (f - CP1N)];
        else v = cur_result[(size_t)s * 2 + (f - CP1N - DCC)];
        xin[si][f] = v;
    }
    __syncthreads();
    int m = blockIdx.y * 256 + tid;
    int q = m & 3, j = m >> 2;
    float b = lstm_b_ih[q * 256 + j];
    float a0 = b, a1 = b, a2 = b, a3 = b, a4 = b, a5 = b, a6 = b, a7 = b;
    for (int k = 0; k < FEATN; k++) {
        float w = g_LihT[(size_t)k * 1024 + m];
        a0 += xin[0][k] * w; a1 += xin[1][k] * w;
        a2 += xin[2][k] * w; a3 += xin[3][k] * w;
        a4 += xin[4][k] * w; a5 += xin[5][k] * w;
        a6 += xin[6][k] * w; a7 += xin[7][k] * w;
    }
    g_pre[(size_t)(s0 + 0) * 1024 + m] = a0;
    g_pre[(size_t)(s0 + 1) * 1024 + m] = a1;
    g_pre[(size_t)(s0 + 2) * 1024 + m] = a2;
    g_pre[(size_t)(s0 + 3) * 1024 + m] = a3;
    g_pre[(size_t)(s0 + 4) * 1024 + m] = a4;
    g_pre[(size_t)(s0 + 5) * 1024 + m] = a5;
    g_pre[(size_t)(s0 + 6) * 1024 + m] = a6;
    g_pre[(size_t)(s0 + 7) * 1024 + m] = a7;
}

// LSTM recurrence: cluster of 8 CTAs per batch element; double-buffered h,
// ONE cluster barrier per step.
__global__ void __cluster_dims__(8, 1, 1) __launch_bounds__(128, 1)
lstm_rec_kernel(const float* __restrict__ b_hh) {
    extern __shared__ float sml[];
    float* sW = sml;
    float* sh = sml + 256 * 128;
    int tid = threadIdx.x;
    int r = blockIdx.x & 7;
    int b = blockIdx.x >> 3;
    for (int i = tid; i < 256 * 128; i += 128)
        sW[i] = g_WhhP[(size_t)(i >> 7) * 1024 + r * 128 + (i & 127)];
    for (int i = tid; i < 512; i += 128) sh[i] = 0.f;
    int q = tid & 3, jl = tid >> 2;
    int jg = r * 32 + jl;
    float bias = b_hh[q * 256 + jg];
    float c = 0.f;
    uint32_t sh_my0 = smem_u32(&sh[jg]);
    uint32_t sh_my1 = smem_u32(&sh[256 + jg]);
    __syncthreads();
    CLUSTER_BAR();
    int lbase = (tid & 31) & ~3;
    for (int t = 0; t < SLEN; t++) {
        int s = b * SLEN + t;
        const float* shc = sh + 256 * (t & 1);
        uint32_t sh_next = (t & 1) ? sh_my0 : sh_my1;
        float acc = g_pre[(size_t)s * 1024 + r * 128 + tid] + bias;
#pragma unroll 8
        for (int k = 0; k < 256; k++) acc += shc[k] * sW[k * 128 + tid];
        float vi = __shfl_sync(0xffffffffu, acc, lbase + 0);
        float vf = __shfl_sync(0xffffffffu, acc, lbase + 1);
        float vg = __shfl_sync(0xffffffffu, acc, lbase + 2);
        float vo = __shfl_sync(0xffffffffu, acc, lbase + 3);
        if (q == 0) {
            c = sigmoid_fast(vf) * c + sigmoid_fast(vi) * tanh_fast(vg);
            float h = sigmoid_fast(vo) * tanh_fast(c);
            g_hout[(size_t)s * HHID + jg] = h;
#pragma unroll
            for (int dst = 0; dst < 8; dst++) {
                uint32_t rem;
                asm("mapa.shared::cluster.u32 %0, %1, %2;" : "=r"(rem)
                    : "r"(sh_next), "r"(dst));
                asm volatile("st.shared::cluster.f32 [%0], %1;" :: "r"(rem), "f"(h)
                             : "memory");
            }
        }
        CLUSTER_BAR();
    }
}

// ---------------- pred + BCE + final -----------------------------------------
__global__ void pred_kernel(const float* __restrict__ target_c,
                            const float* __restrict__ result,
                            const float* __restrict__ pred_w,
                            const float* __restrict__ pred_b) {
    __shared__ float sh[HHID];
    __shared__ float s_p, s_n;
    int i = blockIdx.x, tid = threadIdx.x;
    sh[tid] = g_hout[(size_t)i * HHID + tid];
    sh[tid + 128] = g_hout[(size_t)i * HHID + tid + 128];
    if (tid == 0) { s_p = 0.f; s_n = 0.f; }
    __syncthreads();
    int warp = tid >> 5, lane = tid & 31;
    float lp = 0.f, ln = 0.f;
    for (int c = warp; c < CP1N; c += 4) {
        float tc = target_c[i * CP1N + c];
        if (tc != 0.f) {
            float s = 0.f;
            for (int d = lane; d < HHID; d += 32) s += pred_w[c * HHID + d] * sh[d];
#pragma unroll
            for (int o = 16; o > 0; o >>= 1) s += __shfl_xor_sync(0xffffffffu, s, o);
            if (lane == 0) { lp += tc * (s + pred_b[c]); ln += tc; }
        }
    }
    if (lane == 0) { atomicAdd(&s_p, lp); atomicAdd(&s_n, ln); }
    __syncthreads();
    if (tid == 0) {
        float nc = s_n;
        int mask = nc > 0.f;
        float fp = s_p / (mask ? nc : 1.f);
        float ft = result[i];
        float bce = fmaxf(fp, 0.f) - fp * ft + log1pf(expf(-fabsf(fp)));
        g_fp[i] = fp;
        g_mf[i] = mask ? 1.f : 0.f;
        g_bce[i] = mask ? bce : 0.f;
    }
}

__global__ void final_kernel(const float* __restrict__ result, float* __restrict__ out,
                             int out_size) {
    __shared__ float rb[256], rm[256];
    int tid = threadIdx.x;
    float sb = 0.f, smm = 0.f;
    for (int i = tid; i < GG; i += 256) { sb += g_bce[i]; smm += g_mf[i]; }
    rb[tid] = sb; rm[tid] = smm;
    __syncthreads();
    for (int o = 128; o > 0; o >>= 1) {
        if (tid < o) { rb[tid] += rb[tid + o]; rm[tid] += rm[tid + o]; }
        __syncthreads();
    }
    if (tid == 0 && out_size > 0) out[0] = rb[0] / fmaxf(rm[0], 1.f);
    for (int i = tid; i < GG; i += 256) {
        if (1 + i < out_size) out[1 + i] = 1.f / (1.f + expf(-g_fp[i]));
        if (1 + GG + i < out_size) out[1 + GG + i] = result[i];
    }
}

// ---------------- launcher ---------------------------------------------------
extern "C" void kernel_launch(void* const* d_in, const int* in_sizes, int n_in,
                              void* d_out, int out_size) {
    const float* c_id       = (const float*)d_in[1];
    const int*   node_id    = (const int*)d_in[2];
    const int*   edge       = (const int*)d_in[3];
    const int*   edge_type  = (const int*)d_in[4];
    const float* target_c   = (const float*)d_in[5];
    const float* result     = (const float*)d_in[6];
    const float* c_embed    = (const float*)d_in[7];
    const float* cur_result = (const float*)d_in[8];
    const float* node_embed_w = (const float*)d_in[9];
    const float* edge_embed_w = (const float*)d_in[10];
    const float* ggnn_w     = (const float*)d_in[11];
    const float* gru_w_ih   = (const float*)d_in[12];
    const float* gru_w_hh   = (const float*)d_in[13];
    const float* gru_b_ih   = (const float*)d_in[14];
    const float* gru_b_hh   = (const float*)d_in[15];
    const float* transdim_w = (const float*)d_in[16];
    const float* concept_embedding = (const float*)d_in[17];
    const float* lstm_w_ih  = (const float*)d_in[18];
    const float* lstm_w_hh  = (const float*)d_in[19];
    const float* lstm_b_ih  = (const float*)d_in[20];
    const float* lstm_b_hh  = (const float*)d_in[21];
    const float* pred_w     = (const float*)d_in[22];
    const float* pred_b     = (const float*)d_in[23];
    float* out = (float*)d_out;
    (void)in_sizes; (void)n_in;

    const int SCAT_SMEM = NNODE * DD * 4;
    const int LSTM_SMEM = 256 * 128 * 4 + 512 * 4;
    const int ATTN_SMEM = (NNODE * 65 + 8 * NNODE + 8 * 64 + NNODE + 64 + 4) * 4;
    cudaFuncSetAttribute(layer_mma, cudaFuncAttributeMaxDynamicSharedMemorySize, SM_TOT);
    cudaFuncSetAttribute(gemm_td, cudaFuncAttributeMaxDynamicSharedMemorySize, TD_TOT);
    cudaFuncSetAttribute(attn_kernel, cudaFuncAttributeMaxDynamicSharedMemorySize, ATTN_SMEM);
    cudaFuncSetAttribute(scatter_csr, cudaFuncAttributeMaxDynamicSharedMemorySize, SCAT_SMEM);
    cudaFuncSetAttribute(lstm_rec_kernel, cudaFuncAttributeMaxDynamicSharedMemorySize,
                         LSTM_SMEM);

    prep_kernel<<<1960, 256>>>(edge_embed_w, gru_w_hh, transdim_w, lstm_w_ih, lstm_w_hh);
    comb_kernel<<<(4 * 384 * 128 + 255) / 256, 256>>>(ggnn_w, gru_w_ih);
    gather_kernel<<<GN / 8, 256>>>(node_id, node_embed_w);
    csr_build<<<GG, 256>>>(edge, edge_type);

    for (int l = 0; l < 4; l++) {
        scatter_csr<<<GG, 512, SCAT_SMEM>>>(0);
        layer_mma<<<GN / 64, 256, SM_TOT>>>(l, gru_b_ih, gru_b_hh);
    }

    gemm_td<<<GN / 128, 256, TD_TOT>>>();
    attn_kernel<<<GG, 256, ATTN_SMEM>>>(c_id, c_embed, concept_embedding);
    lstm_pre_kernel<<<dim3(GG / 8, 4), 256>>>(c_embed, cur_result, lstm_b_ih);
    lstm_rec_kernel<<<BSZ * 8, 128, LSTM_SMEM>>>(lstm_b_hh);
    pred_kernel<<<GG, 128>>>(target_c, result, pred_w, pred_b);
    final_kernel<<<1, 256>>>(result, out, out_size);
}

// round 11
// speedup vs baseline: 1.6597x; 1.1771x over previous
#include <cuda_runtime.h>
#include <cuda_bf16.h>
#include <math.h>
#include <stdint.h>

#define BSZ  8
#define SLEN 100
#define GG   800
#define NNODE 200
#define NEDGE 600
#define DD   128
#define DCC  64
#define HHID 256
#define CP1N 111
#define FEATN 177
#define GN   160000

// ---------------- scratch globals -------------------------------------------
__device__ float g_x[(size_t)GN * DD];
__device__ __nv_bfloat16 g_xhi[(size_t)GN * DD];
__device__ __nv_bfloat16 g_agghi[(size_t)GN * DD];
__device__ __nv_bfloat16 g_CombT_hi[4 * 384 * 128];   // [l][j][k]
__device__ __nv_bfloat16 g_Whh_hi[384 * 128];         // [j][k]
__device__ __nv_bfloat16 g_Td_hi[64 * 128];           // [c][k]
__device__ float g_ggnn[(size_t)GN * DCC];
__device__ float g_attn[GG * DCC];
__device__ float g_mean8[8];
__device__ float g_LihT[FEATN * 1024];
__device__ float g_WhhP[256 * 1024];
__device__ float g_pre[(size_t)GG * 1024];
__device__ float g_hout[(size_t)GG * HHID];
__device__ float g_fp[GG];
__device__ float g_bce[GG];
__device__ float g_mf[GG];
// CSR scratch (layer-invariant)
__device__ int   g_csr_src[GG * NEDGE];
__device__ float g_csr_w[GG * NEDGE];
__device__ int   g_csr_ofs[GG * (NNODE + 1)];

__device__ __forceinline__ float tanh_fast(float x) {
    float y; asm("tanh.approx.f32 %0, %1;" : "=f"(y) : "f"(x)); return y;
}
__device__ __forceinline__ float sigmoid_fast(float x) {
    return fmaf(tanh_fast(0.5f * x), 0.5f, 0.5f);
}

__device__ __forceinline__ uint32_t smem_u32(const void* p) {
    uint32_t a;
    asm("{ .reg .u64 t; cvta.to.shared.u64 t, %1; cvt.u32.u64 %0, t; }" : "=r"(a) : "l"(p));
    return a;
}
__device__ __forceinline__ void ldsm_x4(uint32_t& a0, uint32_t& a1, uint32_t& a2,
                                        uint32_t& a3, uint32_t addr) {
    asm volatile("ldmatrix.sync.aligned.m8n8.x4.shared.b16 {%0,%1,%2,%3}, [%4];"
                 : "=r"(a0), "=r"(a1), "=r"(a2), "=r"(a3) : "r"(addr));
}
__device__ __forceinline__ void mma16816(float* d, uint32_t a0, uint32_t a1, uint32_t a2,
                                         uint32_t a3, uint32_t b0, uint32_t b1) {
    asm volatile("mma.sync.aligned.m16n8k16.row.col.f32.bf16.bf16.f32 "
                 "{%0,%1,%2,%3}, {%4,%5,%6,%7}, {%8,%9}, {%0,%1,%2,%3};"
                 : "+f"(d[0]), "+f"(d[1]), "+f"(d[2]), "+f"(d[3])
                 : "r"(a0), "r"(a1), "r"(a2), "r"(a3), "r"(b0), "r"(b1));
}
__device__ __forceinline__ void cp_async16(uint32_t saddr, const void* gaddr) {
    asm volatile("cp.async.cg.shared.global [%0], [%1], 16;" :: "r"(saddr), "l"(gaddr));
}
#define CP_COMMIT() asm volatile("cp.async.commit_group;" ::: "memory")
#define CP_WAIT(n)  asm volatile("cp.async.wait_group %0;" :: "n"(n) : "memory")
#define CLUSTER_BAR() do { \
    asm volatile("barrier.cluster.arrive.aligned;" ::: "memory"); \
    asm volatile("barrier.cluster.wait.aligned;" ::: "memory"); \
} while (0)

// ---------------- prep -------------------------------------------------------
__global__ void prep_kernel(const float* __restrict__ edge_embed_w,
                            const float* __restrict__ gru_w_hh,
                            const float* __restrict__ transdim_w,
                            const float* __restrict__ lstm_w_ih,
                            const float* __restrict__ lstm_w_hh) {
    const int T3 = 64 * 128, T4 = FEATN * 1024, T5 = 256 * 1024, T6 = 384 * 128;
    int total = 8 + T3 + T4 + T5 + T6;
    for (int i = blockIdx.x * blockDim.x + threadIdx.x; i < total;
         i += gridDim.x * blockDim.x) {
        int t = i;
        if (t < 8) {
            float s = 0.f;
            for (int d = 0; d < DD; d++) s += edge_embed_w[t * DD + d];
            g_mean8[t] = s / (float)DD;
            continue;
        }
        t -= 8;
        if (t < T3) { g_Td_hi[t] = __float2bfloat16_rn(transdim_w[t]); continue; }
        t -= T3;
        if (t < T4) {
            int k = t / 1024, p = t % 1024; int q = p & 3, j = p >> 2;
            g_LihT[t] = lstm_w_ih[(q * 256 + j) * FEATN + k];
            continue;
        }
        t -= T4;
        if (t < T5) {
            int k = t / 1024, p = t % 1024; int q = p & 3, j = p >> 2;
            g_WhhP[t] = lstm_w_hh[(q * 256 + j) * 256 + k];
            continue;
        }
        t -= T5;
        g_Whh_hi[t] = __float2bfloat16_rn(gru_w_hh[t]);
    }
}

// CombT[l][j][k] = sum_d W_l[k,d] * W_ih[j,d]
__global__ void comb_kernel(const float* __restrict__ ggnn_w,
                            const float* __restrict__ gru_w_ih) {
    int t = blockIdx.x * blockDim.x + threadIdx.x;
    if (t >= 4 * 384 * 128) return;
    int l = t / (384 * 128); int r = t % (384 * 128);
    int j = r / 128, k = r % 128;
    const float4* wl = (const float4*)(ggnn_w + ((size_t)l * 128 + k) * 128);
    const float4* wi = (const float4*)(gru_w_ih + (size_t)j * 128);
    float s = 0.f;
#pragma unroll 8
    for (int d = 0; d < 32; d++) {
        float4 a = wl[d], b = wi[d];
        s += a.x * b.x + a.y * b.y + a.z * b.z + a.w * b.w;
    }
    g_CombT_hi[t] = __float2bfloat16_rn(s);
}

// ---------------- gather -----------------------------------------------------
__global__ void gather_kernel(const int* __restrict__ node_id,
                              const float* __restrict__ embed) {
    int warp = threadIdx.x >> 5, lane = threadIdx.x & 31;
    int row = blockIdx.x * 8 + warp;
    if (row >= GN) return;
    int nid = node_id[row];
    float4 v = *(const float4*)&embed[(size_t)nid * DD + lane * 4];
    size_t o = (size_t)row * DD + lane * 4;
    *(float4*)&g_x[o] = v;
    ((__nv_bfloat162*)&g_xhi[o])[0] =
        __nv_bfloat162(__float2bfloat16_rn(v.x), __float2bfloat16_rn(v.y));
    ((__nv_bfloat162*)&g_xhi[o])[1] =
        __nv_bfloat162(__float2bfloat16_rn(v.z), __float2bfloat16_rn(v.w));
}

// ---------------- CSR build (once; layer-invariant) --------------------------
__global__ void csr_build(const int* __restrict__ edge,
                          const int* __restrict__ edge_type) {
    __shared__ int s_src[NEDGE];
    __shared__ int s_dst[NEDGE];
    __shared__ int cnt[NNODE + 1];
    __shared__ int ofs[NNODE + 1];
    __shared__ float sm8[8];
    int g = blockIdx.x;
    int tid = threadIdx.x;
    const int* eg = edge + (size_t)g * 2 * NEDGE;
    if (tid < 8) sm8[tid] = g_mean8[tid];
    for (int e = tid; e < NEDGE; e += 256) { s_src[e] = eg[e]; s_dst[e] = eg[NEDGE + e]; }
    for (int i = tid; i <= NNODE; i += 256) cnt[i] = 0;
    __syncthreads();
    for (int e = tid; e < NEDGE; e += 256) atomicAdd(&cnt[s_dst[e]], 1);
    __syncthreads();
    if (tid == 0) {
        int acc = 0;
        for (int n = 0; n <= NNODE; n++) { int c = cnt[n]; ofs[n] = acc; acc += c; }
    }
    __syncthreads();
    for (int i = tid; i <= NNODE; i += 256) g_csr_ofs[g * (NNODE + 1) + i] = ofs[i];
    for (int i = tid; i < NNODE; i += 256) cnt[i] = ofs[i];
    __syncthreads();
    for (int e = tid; e < NEDGE; e += 256) {
        int p = atomicAdd(&cnt[s_dst[e]], 1);
        g_csr_src[g * NEDGE + p] = s_src[e];
        g_csr_w[g * NEDGE + p] = sm8[edge_type[(size_t)g * NEDGE + e]];
    }
}

// ---------------- per-layer edge scatter: smem x tile + prebuilt CSR ---------
__global__ void __launch_bounds__(512, 2) scatter_csr(int dummy) {
    extern __shared__ float sx[];
    int g = blockIdx.x;
    int tid = threadIdx.x;
    {
        const float4* xg4 = (const float4*)(g_x + (size_t)g * NNODE * DD);
        float4* sx4 = (float4*)sx;
        for (int i = tid; i < NNODE * DD / 4; i += 512) sx4[i] = xg4[i];
    }
    __syncthreads();
    int warp = tid >> 5, lane = tid & 31;
    const int* ofs = g_csr_ofs + g * (NNODE + 1);
    const int* srcv = g_csr_src + g * NEDGE;
    const float* wv = g_csr_w + g * NEDGE;
    for (int n = warp; n < NNODE; n += 16) {
        float4 acc = make_float4(0.f, 0.f, 0.f, 0.f);
        int s0 = ofs[n], s1 = ofs[n + 1];
        for (int i = s0; i < s1; i++) {
            int src = srcv[i];
            float w = wv[i];
            float4 v = *(const float4*)&sx[src * DD + lane * 4];
            acc.x += w * v.x; acc.y += w * v.y; acc.z += w * v.z; acc.w += w * v.w;
        }
        size_t o = ((size_t)(g * NNODE + n)) * DD + lane * 4;
        ((__nv_bfloat162*)&g_agghi[o])[0] =
            __nv_bfloat162(__float2bfloat16_rn(acc.x), __float2bfloat16_rn(acc.y));
        ((__nv_bfloat162*)&g_agghi[o])[1] =
            __nv_bfloat162(__float2bfloat16_rn(acc.z), __float2bfloat16_rn(acc.w));
    }
    (void)dummy;
}

// ---------------- fused HMMA GGNN layer: 1-pass bf16 -------------------------
#define SMA_AGH 0
#define SMA_XH  16384
#define SMB0    32768
#define SMB1    65536
#define SMB_BIA 98304
#define SM_TOT  (98304 + 2048)

__global__ void __launch_bounds__(256, 1) layer_mma(int layer,
                                                    const float* __restrict__ b_ih,
                                                    const float* __restrict__ b_hh) {
    extern __shared__ __align__(128) char smx[];
    uint32_t sbase = smem_u32(smx);
    int tid = threadIdx.x, wid = tid >> 5, lane = tid & 31;
    int rowBase = blockIdx.x * 64;
    int rg = wid >> 1;
    int cg = wid & 1;
    float* sb = (float*)(smx + SMB_BIA);
    if (tid < 128) {
        sb[tid]       = b_ih[tid] + b_hh[tid];
        sb[128 + tid] = b_ih[128 + tid] + b_hh[128 + tid];
        sb[256 + tid] = b_ih[256 + tid];
        sb[384 + tid] = b_hh[256 + tid];
    }
    {
        const __nv_bfloat16* s0 = g_agghi + (size_t)rowBase * 128;
        const __nv_bfloat16* s2 = g_xhi + (size_t)rowBase * 128;
#pragma unroll
        for (int q = 0; q < 4; q++) {
            int i = tid + 256 * q;
            int r = i >> 4, c = i & 15;
            uint32_t off = r * 256 + ((c ^ (r & 7)) << 4);
            cp_async16(sbase + SMA_AGH + off, s0 + i * 8);
            cp_async16(sbase + SMA_XH + off, s2 + i * 8);
        }
    }
    auto load_b = [&](int c) {
        int j0 = (c >> 1) * 128;
        bool isComb = !(c & 1);
        const __nv_bfloat16* bh = isComb ? (g_CombT_hi + ((size_t)layer * 384 + j0) * 128)
                                         : (g_Whh_hi + (size_t)j0 * 128);
        uint32_t dst = sbase + ((c & 1) ? SMB1 : SMB0);
#pragma unroll
        for (int q = 0; q < 8; q++) {
            int i = tid + 256 * q;
            int r = i >> 4, cc = i & 15;
            uint32_t off = r * 256 + ((cc ^ (r & 7)) << 4);
            cp_async16(dst + off, bh + i * 8);
        }
    };
    load_b(0);
    CP_COMMIT();

    float acc[4][8][4];
#pragma unroll
    for (int b = 0; b < 4; b++)
#pragma unroll
        for (int n = 0; n < 8; n++)
#pragma unroll
            for (int e = 0; e < 4; e++) acc[b][n][e] = 0.f;

    const int a_r = rg * 16 + (lane & 15);
    const int a_kh = lane >> 4;
    const int b_grp = lane >> 3;
    const int b_nt_off = b_grp >> 1;
    const int b_kh = b_grp & 1;
    const int b_nl = lane & 7;

#pragma unroll
    for (int chunk = 0; chunk < 6; chunk++) {
        if (chunk < 5) { load_b(chunk + 1); CP_COMMIT(); }
        if (chunk < 5) { CP_WAIT(1); } else { CP_WAIT(0); }
        __syncthreads();
        const bool isComb = !(chunk & 1);
        const int bank = (chunk < 2) ? 0 : (chunk < 4) ? 1 : (chunk == 4) ? 2 : 3;
        const uint32_t bufH = sbase + ((chunk & 1) ? SMB1 : SMB0);
        const uint32_t aHi = sbase + (isComb ? SMA_AGH : SMA_XH);
        for (int ks = 0; ks < 8; ks++) {
            uint32_t ach = (uint32_t)(((ks * 2 + a_kh) ^ (a_r & 7)) << 4) + a_r * 256;
            uint32_t ah0, ah1, ah2, ah3;
            ldsm_x4(ah0, ah1, ah2, ah3, aHi + ach);
#pragma unroll
            for (int nt2 = 0; nt2 < 8; nt2 += 2) {
                int n = cg * 64 + (nt2 + b_nt_off) * 8 + b_nl;
                uint32_t boff = (uint32_t)n * 256 + (uint32_t)(((ks * 2 + b_kh) ^ (n & 7)) << 4);
                uint32_t bh0, bh1, bh2, bh3;
                ldsm_x4(bh0, bh1, bh2, bh3, bufH + boff);
                mma16816(acc[bank][nt2], ah0, ah1, ah2, ah3, bh0, bh1);
                mma16816(acc[bank][nt2 + 1], ah0, ah1, ah2, ah3, bh2, bh3);
            }
        }
        __syncthreads();
    }

    int tq = lane >> 2, tr = lane & 3;
#pragma unroll
    for (int nt = 0; nt < 8; nt++) {
        int j = cg * 64 + nt * 8 + tr * 2;
#pragma unroll
        for (int h = 0; h < 2; h++) {
            int m = rowBase + rg * 16 + tq + h * 8;
            float r0 = sigmoid_fast(acc[0][nt][2 * h] + sb[j]);
            float r1 = sigmoid_fast(acc[0][nt][2 * h + 1] + sb[j + 1]);
            float z0 = sigmoid_fast(acc[1][nt][2 * h] + sb[128 + j]);
            float z1 = sigmoid_fast(acc[1][nt][2 * h + 1] + sb[128 + j + 1]);
            float n0 = tanh_fast(acc[2][nt][2 * h] + sb[256 + j] +
                             r0 * (acc[3][nt][2 * h] + sb[384 + j]));
            float n1 = tanh_fast(acc[2][nt][2 * h + 1] + sb[256 + j + 1] +
                             r1 * (acc[3][nt][2 * h + 1] + sb[384 + j + 1]));
            size_t o = (size_t)m * 128 + j;
            float2 xo = *(const float2*)&g_x[o];
            float xn0 = fmaf(z0, xo.x - n0, n0);
            float xn1 = fmaf(z1, xo.y - n1, n1);
            *(float2*)&g_x[o] = make_float2(xn0, xn1);
            *(__nv_bfloat162*)&g_xhi[o] =
                __nv_bfloat162(__float2bfloat16_rn(xn0), __float2bfloat16_rn(xn1));
        }
    }
}

// ---------------- transdim GEMM via HMMA (1-pass) -----------------------------
#define TD_AH 0
#define TD_BH 32768
#define TD_TOT 49152
__global__ void __launch_bounds__(256, 2) gemm_td() {
    extern __shared__ __align__(128) char smt[];
    uint32_t sbase = smem_u32(smt);
    int tid = threadIdx.x, wid = tid >> 5, lane = tid & 31;
    int rowBase = blockIdx.x * 128;
    {
        const __nv_bfloat16* s2 = g_xhi + (size_t)rowBase * 128;
#pragma unroll
        for (int q = 0; q < 8; q++) {
            int i = tid + 256 * q;
            int r = i >> 4, c = i & 15;
            uint32_t off = r * 256 + ((c ^ (r & 7)) << 4);
            cp_async16(sbase + TD_AH + off, s2 + i * 8);
        }
    }
    {
#pragma unroll
        for (int q = 0; q < 4; q++) {
            int i = tid + 256 * q;
            int r = i >> 4, c = i & 15;
            uint32_t off = r * 256 + ((c ^ (r & 7)) << 4);
            cp_async16(sbase + TD_BH + off, g_Td_hi + i * 8);
        }
    }
    CP_COMMIT();
    CP_WAIT(0);
    __syncthreads();

    float acc[8][4];
#pragma unroll
    for (int n = 0; n < 8; n++)
#pragma unroll
        for (int e = 0; e < 4; e++) acc[n][e] = 0.f;

    const int a_r = wid * 16 + (lane & 15);
    const int a_kh = lane >> 4;
    const int b_grp = lane >> 3;
    const int b_nt_off = b_grp >> 1;
    const int b_kh = b_grp & 1;
    const int b_nl = lane & 7;

    for (int ks = 0; ks < 8; ks++) {
        uint32_t ach = (uint32_t)(((ks * 2 + a_kh) ^ (a_r & 7)) << 4) + a_r * 256;
        uint32_t ah0, ah1, ah2, ah3;
        ldsm_x4(ah0, ah1, ah2, ah3, sbase + TD_AH + ach);
#pragma unroll
        for (int nt2 = 0; nt2 < 8; nt2 += 2) {
            int n = (nt2 + b_nt_off) * 8 + b_nl;
            uint32_t boff = (uint32_t)n * 256 + (uint32_t)(((ks * 2 + b_kh) ^ (n & 7)) << 4);
            uint32_t bh0, bh1, bh2, bh3;
            ldsm_x4(bh0, bh1, bh2, bh3, sbase + TD_BH + boff);
            mma16816(acc[nt2], ah0, ah1, ah2, ah3, bh0, bh1);
            mma16816(acc[nt2 + 1], ah0, ah1, ah2, ah3, bh2, bh3);
        }
    }
    int tq = lane >> 2, tr = lane & 3;
#pragma unroll
    for (int nt = 0; nt < 8; nt++) {
        int j = nt * 8 + tr * 2;
#pragma unroll
        for (int h = 0; h < 2; h++) {
            int m = rowBase + wid * 16 + tq + h * 8;
            *(float2*)&g_ggnn[(size_t)m * DCC + j] =
                make_float2(acc[nt][2 * h], acc[nt][2 * h + 1]);
        }
    }
}

// ---------------- attention (collapsed node weights) --------------------------
__global__ void attn_kernel(const float* __restrict__ c_id,
                            const float* __restrict__ c_embed,
                            const float* __restrict__ concept_embedding) {
    extern __shared__ float smf[];
    float* shg = smf;
    float* pbuf = shg + NNODE * 65;
    float* qbuf = pbuf + 8 * NNODE;
    float* wnode = qbuf + 8 * 64;
    float* accd = wnode + NNODE;
    float* snum = accd + 64;
    int g = blockIdx.x;
    int tid = threadIdx.x;
    for (int i = tid; i < NNODE * DCC; i += 256) {
        int n = i >> 6, d = i & 63;
        shg[n * 65 + d] = g_ggnn[(size_t)(g * NNODE + n) * DCC + d];
    }
    for (int i = tid; i < NNODE; i += 256) wnode[i] = 0.f;
    if (tid < 64) accd[tid] = 0.f;
    if (tid == 0) snum[0] = 0.f;
    __syncthreads();
    if (tid < CP1N) atomicAdd(snum, c_id[g * CP1N + tid]);
    __syncthreads();
    int warp = tid >> 5, lane = tid & 31;
    for (int c = warp; c < CP1N; c += 8) {
        float ce = c_embed[g * CP1N + c];
        if (ce == 0.f) continue;
        qbuf[warp * 64 + lane] = ce * concept_embedding[c * DCC + lane];
        qbuf[warp * 64 + lane + 32] = ce * concept_embedding[c * DCC + lane + 32];
        __syncwarp();
        float mx = -1e30f;
        for (int n = lane; n < NNODE; n += 32) {
            float s = 0.f;
#pragma unroll 16
            for (int d = 0; d < DCC; d++) s += qbuf[warp * 64 + d] * shg[n * 65 + d];
            pbuf[warp * NNODE + n] = s;
            mx = fmaxf(mx, s);
        }
#pragma unroll
        for (int o = 16; o > 0; o >>= 1) mx = fmaxf(mx, __shfl_xor_sync(0xffffffffu, mx, o));
        float ssum = 0.f;
        for (int n = lane; n < NNODE; n += 32) {
            float p = expf(pbuf[warp * NNODE + n] - mx);
            pbuf[warp * NNODE + n] = p;
            ssum += p;
        }
#pragma unroll
        for (int o = 16; o > 0; o >>= 1) ssum += __shfl_xor_sync(0xffffffffu, ssum, o);
        float inv = ce / ssum;
        for (int n = lane; n < NNODE; n += 32)
            atomicAdd(&wnode[n], inv * pbuf[warp * NNODE + n]);
    }
    __syncthreads();
    {
        int d = tid & 63, q = tid >> 6;
        float partial = 0.f;
        for (int n = q * 50; n < q * 50 + 50; n++)
            partial += wnode[n] * shg[n * 65 + d];
        atomicAdd(&accd[d], partial);
    }
    __syncthreads();
    if (tid < DCC) {
        float nv = snum[0];
        if (nv == 0.f) nv = 1.f;
        g_attn[g * DCC + tid] = accd[tid] / nv;
    }
}

// ---------------- LSTM input GEMM: 8 sequences per block ---------------------
__global__ void lstm_pre_kernel(const float* __restrict__ c_embed,
                                const float* __restrict__ cur_result,
                                const float* __restrict__ lstm_b_ih) {
    __shared__ float xin[8][FEATN];
    int s0 = blockIdx.x * 8;
    int tid = threadIdx.x;
    for (int i = tid; i < 8 * FEATN; i += 256) {
        int si = i / FEATN, f = i % FEATN;
        int s = s0 + si;
        float v;
        if (f < CP1N) v = c_embed[(size_t)s * CP1N + f];
        else if (f < CP1N + DCC) v = g_attn[(size_t)s * DCC + (f - CP1N)];
        else v = cur_result[(size_t)s * 2 + (f - CP1N - DCC)];
        xin[si][f] = v;
    }
    __syncthreads();
    int m = blockIdx.y * 256 + tid;
    int q = m & 3, j = m >> 2;
    float b = lstm_b_ih[q * 256 + j];
    float a0 = b, a1 = b, a2 = b, a3 = b, a4 = b, a5 = b, a6 = b, a7 = b;
    for (int k = 0; k < FEATN; k++) {
        float w = g_LihT[(size_t)k * 1024 + m];
        a0 += xin[0][k] * w; a1 += xin[1][k] * w;
        a2 += xin[2][k] * w; a3 += xin[3][k] * w;
        a4 += xin[4][k] * w; a5 += xin[5][k] * w;
        a6 += xin[6][k] * w; a7 += xin[7][k] * w;
    }
    g_pre[(size_t)(s0 + 0) * 1024 + m] = a0;
    g_pre[(size_t)(s0 + 1) * 1024 + m] = a1;
    g_pre[(size_t)(s0 + 2) * 1024 + m] = a2;
    g_pre[(size_t)(s0 + 3) * 1024 + m] = a3;
    g_pre[(size_t)(s0 + 4) * 1024 + m] = a4;
    g_pre[(size_t)(s0 + 5) * 1024 + m] = a5;
    g_pre[(size_t)(s0 + 6) * 1024 + m] = a6;
    g_pre[(size_t)(s0 + 7) * 1024 + m] = a7;
}

// LSTM recurrence: cluster of 8 CTAs per batch element; double-buffered h,
// ONE cluster barrier per step.
__global__ void __cluster_dims__(8, 1, 1) __launch_bounds__(128, 1)
lstm_rec_kernel(const float* __restrict__ b_hh) {
    extern __shared__ float sml[];
    float* sW = sml;
    float* sh = sml + 256 * 128;
    int tid = threadIdx.x;
    int r = blockIdx.x & 7;
    int b = blockIdx.x >> 3;
    for (int i = tid; i < 256 * 128; i += 128)
        sW[i] = g_WhhP[(size_t)(i >> 7) * 1024 + r * 128 + (i & 127)];
    for (int i = tid; i < 512; i += 128) sh[i] = 0.f;
    int q = tid & 3, jl = tid >> 2;
    int jg = r * 32 + jl;
    float bias = b_hh[q * 256 + jg];
    float c = 0.f;
    uint32_t sh_my0 = smem_u32(&sh[jg]);
    uint32_t sh_my1 = smem_u32(&sh[256 + jg]);
    __syncthreads();
    CLUSTER_BAR();
    int lbase = (tid & 31) & ~3;
    for (int t = 0; t < SLEN; t++) {
        int s = b * SLEN + t;
        const float* shc = sh + 256 * (t & 1);
        uint32_t sh_next = (t & 1) ? sh_my0 : sh_my1;
        float acc = g_pre[(size_t)s * 1024 + r * 128 + tid] + bias;
#pragma unroll 8
        for (int k = 0; k < 256; k++) acc += shc[k] * sW[k * 128 + tid];
        float vi = __shfl_sync(0xffffffffu, acc, lbase + 0);
        float vf = __shfl_sync(0xffffffffu, acc, lbase + 1);
        float vg = __shfl_sync(0xffffffffu, acc, lbase + 2);
        float vo = __shfl_sync(0xffffffffu, acc, lbase + 3);
        if (q == 0) {
            c = sigmoid_fast(vf) * c + sigmoid_fast(vi) * tanh_fast(vg);
            float h = sigmoid_fast(vo) * tanh_fast(c);
            g_hout[(size_t)s * HHID + jg] = h;
#pragma unroll
            for (int dst = 0; dst < 8; dst++) {
                uint32_t rem;
                asm("mapa.shared::cluster.u32 %0, %1, %2;" : "=r"(rem)
                    : "r"(sh_next), "r"(dst));
                asm volatile("st.shared::cluster.f32 [%0], %1;" :: "r"(rem), "f"(h)
                             : "memory");
            }
        }
        CLUSTER_BAR();
    }
}

// ---------------- pred + BCE + final -----------------------------------------
__global__ void pred_kernel(const float* __restrict__ target_c,
                            const float* __restrict__ result,
                            const float* __restrict__ pred_w,
                            const float* __restrict__ pred_b) {
    __shared__ float sh[HHID];
    __shared__ float s_p, s_n;
    int i = blockIdx.x, tid = threadIdx.x;
    sh[tid] = g_hout[(size_t)i * HHID + tid];
    sh[tid + 128] = g_hout[(size_t)i * HHID + tid + 128];
    if (tid == 0) { s_p = 0.f; s_n = 0.f; }
    __syncthreads();
    int warp = tid >> 5, lane = tid & 31;
    float lp = 0.f, ln = 0.f;
    for (int c = warp; c < CP1N; c += 4) {
        float tc = target_c[i * CP1N + c];
        if (tc != 0.f) {
            float s = 0.f;
            for (int d = lane; d < HHID; d += 32) s += pred_w[c * HHID + d] * sh[d];
#pragma unroll
            for (int o = 16; o > 0; o >>= 1) s += __shfl_xor_sync(0xffffffffu, s, o);
            if (lane == 0) { lp += tc * (s + pred_b[c]); ln += tc; }
        }
    }
    if (lane == 0) { atomicAdd(&s_p, lp); atomicAdd(&s_n, ln); }
    __syncthreads();
    if (tid == 0) {
        float nc = s_n;
        int mask = nc > 0.f;
        float fp = s_p / (mask ? nc : 1.f);
        float ft = result[i];
        float bce = fmaxf(fp, 0.f) - fp * ft + log1pf(expf(-fabsf(fp)));
        g_fp[i] = fp;
        g_mf[i] = mask ? 1.f : 0.f;
        g_bce[i] = mask ? bce : 0.f;
    }
}

__global__ void final_kernel(const float* __restrict__ result, float* __restrict__ out,
                             int out_size) {
    __shared__ float rb[256], rm[256];
    int tid = threadIdx.x;
    float sb = 0.f, smm = 0.f;
    for (int i = tid; i < GG; i += 256) { sb += g_bce[i]; smm += g_mf[i]; }
    rb[tid] = sb; rm[tid] = smm;
    __syncthreads();
    for (int o = 128; o > 0; o >>= 1) {
        if (tid < o) { rb[tid] += rb[tid + o]; rm[tid] += rm[tid + o]; }
        __syncthreads();
    }
    if (tid == 0 && out_size > 0) out[0] = rb[0] / fmaxf(rm[0], 1.f);
    for (int i = tid; i < GG; i += 256) {
        if (1 + i < out_size) out[1 + i] = 1.f / (1.f + expf(-g_fp[i]));
        if (1 + GG + i < out_size) out[1 + GG + i] = result[i];
    }
}

// ---------------- launcher ---------------------------------------------------
extern "C" void kernel_launch(void* const* d_in, const int* in_sizes, int n_in,
                              void* d_out, int out_size) {
    const float* c_id       = (const float*)d_in[1];
    const int*   node_id    = (const int*)d_in[2];
    const int*   edge       = (const int*)d_in[3];
    const int*   edge_type  = (const int*)d_in[4];
    const float* target_c   = (const float*)d_in[5];
    const float* result     = (const float*)d_in[6];
    const float* c_embed    = (const float*)d_in[7];
    const float* cur_result = (const float*)d_in[8];
    const float* node_embed_w = (const float*)d_in[9];
    const float* edge_embed_w = (const float*)d_in[10];
    const float* ggnn_w     = (const float*)d_in[11];
    const float* gru_w_ih   = (const float*)d_in[12];
    const float* gru_w_hh   = (const float*)d_in[13];
    const float* gru_b_ih   = (const float*)d_in[14];
    const float* gru_b_hh   = (const float*)d_in[15];
    const float* transdim_w = (const float*)d_in[16];
    const float* concept_embedding = (const float*)d_in[17];
    const float* lstm_w_ih  = (const float*)d_in[18];
    const float* lstm_w_hh  = (const float*)d_in[19];
    const float* lstm_b_ih  = (const float*)d_in[20];
    const float* lstm_b_hh  = (const float*)d_in[21];
    const float* pred_w     = (const float*)d_in[22];
    const float* pred_b     = (const float*)d_in[23];
    float* out = (float*)d_out;
    (void)in_sizes; (void)n_in;

    const int SCAT_SMEM = NNODE * DD * 4;
    const int LSTM_SMEM = 256 * 128 * 4 + 512 * 4;
    const int ATTN_SMEM = (NNODE * 65 + 8 * NNODE + 8 * 64 + NNODE + 64 + 4) * 4;
    cudaFuncSetAttribute(layer_mma, cudaFuncAttributeMaxDynamicSharedMemorySize, SM_TOT);
    cudaFuncSetAttribute(gemm_td, cudaFuncAttributeMaxDynamicSharedMemorySize, TD_TOT);
    cudaFuncSetAttribute(attn_kernel, cudaFuncAttributeMaxDynamicSharedMemorySize, ATTN_SMEM);
    cudaFuncSetAttribute(scatter_csr, cudaFuncAttributeMaxDynamicSharedMemorySize, SCAT_SMEM);
    cudaFuncSetAttribute(lstm_rec_kernel, cudaFuncAttributeMaxDynamicSharedMemorySize,
                         LSTM_SMEM);

    prep_kernel<<<1960, 256>>>(edge_embed_w, gru_w_hh, transdim_w, lstm_w_ih, lstm_w_hh);
    comb_kernel<<<(4 * 384 * 128 + 255) / 256, 256>>>(ggnn_w, gru_w_ih);
    gather_kernel<<<GN / 8, 256>>>(node_id, node_embed_w);
    csr_build<<<GG, 256>>>(edge, edge_type);

    for (int l = 0; l < 4; l++) {
        scatter_csr<<<GG, 512, SCAT_SMEM>>>(0);
        layer_mma<<<GN / 64, 256, SM_TOT>>>(l, gru_b_ih, gru_b_hh);
    }

    gemm_td<<<GN / 128, 256, TD_TOT>>>();
    attn_kernel<<<GG, 256, ATTN_SMEM>>>(c_id, c_embed, concept_embedding);
    lstm_pre_kernel<<<dim3(GG / 8, 4), 256>>>(c_embed, cur_result, lstm_b_ih);
    lstm_rec_kernel<<<BSZ * 8, 128, LSTM_SMEM>>>(lstm_b_hh);
    pred_kernel<<<GG, 128>>>(target_c, result, pred_w, pred_b);
    final_kernel<<<1, 256>>>(result, out, out_size);
}

// round 12
// speedup vs baseline: 2.4319x; 1.4652x over previous
#include <cuda_runtime.h>
#include <cuda_bf16.h>
#include <math.h>
#include <stdint.h>

#define BSZ  8
#define SLEN 100
#define GG   800
#define NNODE 200
#define NEDGE 600
#define DD   128
#define DCC  64
#define HHID 256
#define CP1N 111
#define FEATN 177
#define GN   160000

// ---------------- scratch globals -------------------------------------------
__device__ __nv_bfloat16 g_xhi[(size_t)GN * DD];
__device__ __nv_bfloat16 g_agghi[(size_t)GN * DD];
__device__ __nv_bfloat16 g_CombT_hi[4 * 384 * 128];   // [l][j][k]
__device__ __nv_bfloat16 g_Whh_hi[384 * 128];         // [j][k]
__device__ __nv_bfloat16 g_Td_hi[64 * 128];           // [c][k]
__device__ float g_ggnn[(size_t)GN * DCC];
__device__ float g_attn[GG * DCC];
__device__ float g_mean8[8];
__device__ float g_LihT[FEATN * 1024];
__device__ __nv_bfloat162 g_WhhB[128 * 1024];         // [k2][m] packed (k,k+1)
__device__ float g_pre[(size_t)GG * 1024];
__device__ float g_hout[(size_t)GG * HHID];
__device__ float g_fp[GG];
__device__ float g_bce[GG];
__device__ float g_mf[GG];
// CSR scratch (layer-invariant)
__device__ int   g_csr_src[GG * NEDGE];
__device__ float g_csr_w[GG * NEDGE];
__device__ int   g_csr_ofs[GG * (NNODE + 1)];

__device__ __forceinline__ float tanh_fast(float x) {
    float y; asm("tanh.approx.f32 %0, %1;" : "=f"(y) : "f"(x)); return y;
}
__device__ __forceinline__ float sigmoid_fast(float x) {
    return fmaf(tanh_fast(0.5f * x), 0.5f, 0.5f);
}

__device__ __forceinline__ uint32_t smem_u32(const void* p) {
    uint32_t a;
    asm("{ .reg .u64 t; cvta.to.shared.u64 t, %1; cvt.u32.u64 %0, t; }" : "=r"(a) : "l"(p));
    return a;
}
__device__ __forceinline__ void ldsm_x4(uint32_t& a0, uint32_t& a1, uint32_t& a2,
                                        uint32_t& a3, uint32_t addr) {
    asm volatile("ldmatrix.sync.aligned.m8n8.x4.shared.b16 {%0,%1,%2,%3}, [%4];"
                 : "=r"(a0), "=r"(a1), "=r"(a2), "=r"(a3) : "r"(addr));
}
__device__ __forceinline__ void mma16816(float* d, uint32_t a0, uint32_t a1, uint32_t a2,
                                         uint32_t a3, uint32_t b0, uint32_t b1) {
    asm volatile("mma.sync.aligned.m16n8k16.row.col.f32.bf16.bf16.f32 "
                 "{%0,%1,%2,%3}, {%4,%5,%6,%7}, {%8,%9}, {%0,%1,%2,%3};"
                 : "+f"(d[0]), "+f"(d[1]), "+f"(d[2]), "+f"(d[3])
                 : "r"(a0), "r"(a1), "r"(a2), "r"(a3), "r"(b0), "r"(b1));
}
__device__ __forceinline__ void cp_async16(uint32_t saddr, const void* gaddr) {
    asm volatile("cp.async.cg.shared.global [%0], [%1], 16;" :: "r"(saddr), "l"(gaddr));
}
#define CP_COMMIT() asm volatile("cp.async.commit_group;" ::: "memory")
#define CP_WAIT(n)  asm volatile("cp.async.wait_group %0;" :: "n"(n) : "memory")
#define CLUSTER_BAR() do { \
    asm volatile("barrier.cluster.arrive.aligned;" ::: "memory"); \
    asm volatile("barrier.cluster.wait.aligned;" ::: "memory"); \
} while (0)

// ---------------- prep -------------------------------------------------------
__global__ void prep_kernel(const float* __restrict__ edge_embed_w,
                            const float* __restrict__ gru_w_hh,
                            const float* __restrict__ transdim_w,
                            const float* __restrict__ lstm_w_ih,
                            const float* __restrict__ lstm_w_hh) {
    const int T3 = 64 * 128, T4 = FEATN * 1024, T5 = 128 * 1024, T6 = 384 * 128;
    int total = 8 + T3 + T4 + T5 + T6;
    for (int i = blockIdx.x * blockDim.x + threadIdx.x; i < total;
         i += gridDim.x * blockDim.x) {
        int t = i;
        if (t < 8) {
            float s = 0.f;
            for (int d = 0; d < DD; d++) s += edge_embed_w[t * DD + d];
            g_mean8[t] = s / (float)DD;
            continue;
        }
        t -= 8;
        if (t < T3) { g_Td_hi[t] = __float2bfloat16_rn(transdim_w[t]); continue; }
        t -= T3;
        if (t < T4) {
            int k = t / 1024, p = t % 1024; int q = p & 3, j = p >> 2;
            g_LihT[t] = lstm_w_ih[(q * 256 + j) * FEATN + k];
            continue;
        }
        t -= T4;
        if (t < T5) {
            int k2 = t >> 10, m = t & 1023; int q = m & 3, j = m >> 2;
            float v0 = lstm_w_hh[(q * 256 + j) * 256 + 2 * k2];
            float v1 = lstm_w_hh[(q * 256 + j) * 256 + 2 * k2 + 1];
            g_WhhB[t] = __nv_bfloat162(__float2bfloat16_rn(v0), __float2bfloat16_rn(v1));
            continue;
        }
        t -= T5;
        g_Whh_hi[t] = __float2bfloat16_rn(gru_w_hh[t]);
    }
}

// CombT[l][j][k] = sum_d W_l[k,d] * W_ih[j,d]
__global__ void comb_kernel(const float* __restrict__ ggnn_w,
                            const float* __restrict__ gru_w_ih) {
    int t = blockIdx.x * blockDim.x + threadIdx.x;
    if (t >= 4 * 384 * 128) return;
    int l = t / (384 * 128); int r = t % (384 * 128);
    int j = r / 128, k = r % 128;
    const float4* wl = (const float4*)(ggnn_w + ((size_t)l * 128 + k) * 128);
    const float4* wi = (const float4*)(gru_w_ih + (size_t)j * 128);
    float s = 0.f;
#pragma unroll 8
    for (int d = 0; d < 32; d++) {
        float4 a = wl[d], b = wi[d];
        s += a.x * b.x + a.y * b.y + a.z * b.z + a.w * b.w;
    }
    g_CombT_hi[t] = __float2bfloat16_rn(s);
}

// ---------------- gather (bf16 only) ------------------------------------------
__global__ void gather_kernel(const int* __restrict__ node_id,
                              const float* __restrict__ embed) {
    int warp = threadIdx.x >> 5, lane = threadIdx.x & 31;
    int row = blockIdx.x * 8 + warp;
    if (row >= GN) return;
    int nid = node_id[row];
    float4 v = *(const float4*)&embed[(size_t)nid * DD + lane * 4];
    size_t o = (size_t)row * DD + lane * 4;
    ((__nv_bfloat162*)&g_xhi[o])[0] =
        __nv_bfloat162(__float2bfloat16_rn(v.x), __float2bfloat16_rn(v.y));
    ((__nv_bfloat162*)&g_xhi[o])[1] =
        __nv_bfloat162(__float2bfloat16_rn(v.z), __float2bfloat16_rn(v.w));
}

// ---------------- CSR build (once; layer-invariant) --------------------------
__global__ void csr_build(const int* __restrict__ edge,
                          const int* __restrict__ edge_type) {
    __shared__ int s_src[NEDGE];
    __shared__ int s_dst[NEDGE];
    __shared__ int cnt[NNODE + 1];
    __shared__ int ofs[NNODE + 1];
    __shared__ float sm8[8];
    int g = blockIdx.x;
    int tid = threadIdx.x;
    const int* eg = edge + (size_t)g * 2 * NEDGE;
    if (tid < 8) sm8[tid] = g_mean8[tid];
    for (int e = tid; e < NEDGE; e += 256) { s_src[e] = eg[e]; s_dst[e] = eg[NEDGE + e]; }
    for (int i = tid; i <= NNODE; i += 256) cnt[i] = 0;
    __syncthreads();
    for (int e = tid; e < NEDGE; e += 256) atomicAdd(&cnt[s_dst[e]], 1);
    __syncthreads();
    if (tid == 0) {
        int acc = 0;
        for (int n = 0; n <= NNODE; n++) { int c = cnt[n]; ofs[n] = acc; acc += c; }
    }
    __syncthreads();
    for (int i = tid; i <= NNODE; i += 256) g_csr_ofs[g * (NNODE + 1) + i] = ofs[i];
    for (int i = tid; i < NNODE; i += 256) cnt[i] = ofs[i];
    __syncthreads();
    for (int e = tid; e < NEDGE; e += 256) {
        int p = atomicAdd(&cnt[s_dst[e]], 1);
        g_csr_src[g * NEDGE + p] = s_src[e];
        g_csr_w[g * NEDGE + p] = sm8[edge_type[(size_t)g * NEDGE + e]];
    }
}

// ---------------- per-layer edge scatter: bf16 smem tile + prebuilt CSR ------
__global__ void __launch_bounds__(512, 3) scatter_csr(int dummy) {
    extern __shared__ __nv_bfloat16 sxb[];   // 200*128 bf16 = 51200 B
    int g = blockIdx.x;
    int tid = threadIdx.x;
    {
        const uint4* xg4 = (const uint4*)(g_xhi + (size_t)g * NNODE * DD);
        uint4* sx4 = (uint4*)sxb;
        for (int i = tid; i < NNODE * DD / 8; i += 512) sx4[i] = xg4[i];
    }
    __syncthreads();
    int warp = tid >> 5, lane = tid & 31;
    const int* ofs = g_csr_ofs + g * (NNODE + 1);
    const int* srcv = g_csr_src + g * NEDGE;
    const float* wv = g_csr_w + g * NEDGE;
    for (int n = warp; n < NNODE; n += 16) {
        float4 acc = make_float4(0.f, 0.f, 0.f, 0.f);
        int s0 = ofs[n], s1 = ofs[n + 1];
        for (int i = s0; i < s1; i++) {
            int src = srcv[i];
            float w = wv[i];
            const __nv_bfloat162* vp = (const __nv_bfloat162*)&sxb[src * DD + lane * 4];
            float2 v0 = __bfloat1622float2(vp[0]);
            float2 v1 = __bfloat1622float2(vp[1]);
            acc.x += w * v0.x; acc.y += w * v0.y; acc.z += w * v1.x; acc.w += w * v1.y;
        }
        size_t o = ((size_t)(g * NNODE + n)) * DD + lane * 4;
        ((__nv_bfloat162*)&g_agghi[o])[0] =
            __nv_bfloat162(__float2bfloat16_rn(acc.x), __float2bfloat16_rn(acc.y));
        ((__nv_bfloat162*)&g_agghi[o])[1] =
            __nv_bfloat162(__float2bfloat16_rn(acc.z), __float2bfloat16_rn(acc.w));
    }
    (void)dummy;
}

// ---------------- fused HMMA GGNN layer: 1-pass bf16, xo from smem -----------
#define SMA_AGH 0
#define SMA_XH  16384
#define SMB0    32768
#define SMB1    65536
#define SMB_BIA 98304
#define SM_TOT  (98304 + 2048)

__global__ void __launch_bounds__(256, 1) layer_mma(int layer,
                                                    const float* __restrict__ b_ih,
                                                    const float* __restrict__ b_hh) {
    extern __shared__ __align__(128) char smx[];
    uint32_t sbase = smem_u32(smx);
    int tid = threadIdx.x, wid = tid >> 5, lane = tid & 31;
    int rowBase = blockIdx.x * 64;
    int rg = wid >> 1;
    int cg = wid & 1;
    float* sb = (float*)(smx + SMB_BIA);
    if (tid < 128) {
        sb[tid]       = b_ih[tid] + b_hh[tid];
        sb[128 + tid] = b_ih[128 + tid] + b_hh[128 + tid];
        sb[256 + tid] = b_ih[256 + tid];
        sb[384 + tid] = b_hh[256 + tid];
    }
    {
        const __nv_bfloat16* s0 = g_agghi + (size_t)rowBase * 128;
        const __nv_bfloat16* s2 = g_xhi + (size_t)rowBase * 128;
#pragma unroll
        for (int q = 0; q < 4; q++) {
            int i = tid + 256 * q;
            int r = i >> 4, c = i & 15;
            uint32_t off = r * 256 + ((c ^ (r & 7)) << 4);
            cp_async16(sbase + SMA_AGH + off, s0 + i * 8);
            cp_async16(sbase + SMA_XH + off, s2 + i * 8);
        }
    }
    auto load_b = [&](int c) {
        int j0 = (c >> 1) * 128;
        bool isComb = !(c & 1);
        const __nv_bfloat16* bh = isComb ? (g_CombT_hi + ((size_t)layer * 384 + j0) * 128)
                                         : (g_Whh_hi + (size_t)j0 * 128);
        uint32_t dst = sbase + ((c & 1) ? SMB1 : SMB0);
#pragma unroll
        for (int q = 0; q < 8; q++) {
            int i = tid + 256 * q;
            int r = i >> 4, cc = i & 15;
            uint32_t off = r * 256 + ((cc ^ (r & 7)) << 4);
            cp_async16(dst + off, bh + i * 8);
        }
    };
    load_b(0);
    CP_COMMIT();

    float acc[4][8][4];
#pragma unroll
    for (int b = 0; b < 4; b++)
#pragma unroll
        for (int n = 0; n < 8; n++)
#pragma unroll
            for (int e = 0; e < 4; e++) acc[b][n][e] = 0.f;

    const int a_r = rg * 16 + (lane & 15);
    const int a_kh = lane >> 4;
    const int b_grp = lane >> 3;
    const int b_nt_off = b_grp >> 1;
    const int b_kh = b_grp & 1;
    const int b_nl = lane & 7;

#pragma unroll
    for (int chunk = 0; chunk < 6; chunk++) {
        if (chunk < 5) { load_b(chunk + 1); CP_COMMIT(); }
        if (chunk < 5) { CP_WAIT(1); } else { CP_WAIT(0); }
        __syncthreads();
        const bool isComb = !(chunk & 1);
        const int bank = (chunk < 2) ? 0 : (chunk < 4) ? 1 : (chunk == 4) ? 2 : 3;
        const uint32_t bufH = sbase + ((chunk & 1) ? SMB1 : SMB0);
        const uint32_t aHi = sbase + (isComb ? SMA_AGH : SMA_XH);
        for (int ks = 0; ks < 8; ks++) {
            uint32_t ach = (uint32_t)(((ks * 2 + a_kh) ^ (a_r & 7)) << 4) + a_r * 256;
            uint32_t ah0, ah1, ah2, ah3;
            ldsm_x4(ah0, ah1, ah2, ah3, aHi + ach);
#pragma unroll
            for (int nt2 = 0; nt2 < 8; nt2 += 2) {
                int n = cg * 64 + (nt2 + b_nt_off) * 8 + b_nl;
                uint32_t boff = (uint32_t)n * 256 + (uint32_t)(((ks * 2 + b_kh) ^ (n & 7)) << 4);
                uint32_t bh0, bh1, bh2, bh3;
                ldsm_x4(bh0, bh1, bh2, bh3, bufH + boff);
                mma16816(acc[bank][nt2], ah0, ah1, ah2, ah3, bh0, bh1);
                mma16816(acc[bank][nt2 + 1], ah0, ah1, ah2, ah3, bh2, bh3);
            }
        }
        __syncthreads();
    }

    // GRU epilogue: xo read from resident smem x tile (un-swizzle)
    int tq = lane >> 2, tr = lane & 3;
#pragma unroll
    for (int nt = 0; nt < 8; nt++) {
        int j = cg * 64 + nt * 8 + tr * 2;
        int cch = j >> 3;
        uint32_t jlow = (uint32_t)((j * 2) & 15);
#pragma unroll
        for (int h = 0; h < 2; h++) {
            int rloc = rg * 16 + tq + h * 8;
            int m = rowBase + rloc;
            float r0 = sigmoid_fast(acc[0][nt][2 * h] + sb[j]);
            float r1 = sigmoid_fast(acc[0][nt][2 * h + 1] + sb[j + 1]);
            float z0 = sigmoid_fast(acc[1][nt][2 * h] + sb[128 + j]);
            float z1 = sigmoid_fast(acc[1][nt][2 * h + 1] + sb[128 + j + 1]);
            float n0 = tanh_fast(acc[2][nt][2 * h] + sb[256 + j] +
                             r0 * (acc[3][nt][2 * h] + sb[384 + j]));
            float n1 = tanh_fast(acc[2][nt][2 * h + 1] + sb[256 + j + 1] +
                             r1 * (acc[3][nt][2 * h + 1] + sb[384 + j + 1]));
            uint32_t xoff = (uint32_t)rloc * 256 +
                            (uint32_t)(((cch ^ (rloc & 7)) << 4)) + jlow;
            float2 xo = __bfloat1622float2(
                *(const __nv_bfloat162*)(smx + SMA_XH + xoff));
            float xn0 = fmaf(z0, xo.x - n0, n0);
            float xn1 = fmaf(z1, xo.y - n1, n1);
            size_t o = (size_t)m * 128 + j;
            *(__nv_bfloat162*)&g_xhi[o] =
                __nv_bfloat162(__float2bfloat16_rn(xn0), __float2bfloat16_rn(xn1));
        }
    }
}

// ---------------- transdim GEMM via HMMA (1-pass) -----------------------------
#define TD_AH 0
#define TD_BH 32768
#define TD_TOT 49152
__global__ void __launch_bounds__(256, 2) gemm_td() {
    extern __shared__ __align__(128) char smt[];
    uint32_t sbase = smem_u32(smt);
    int tid = threadIdx.x, wid = tid >> 5, lane = tid & 31;
    int rowBase = blockIdx.x * 128;
    {
        const __nv_bfloat16* s2 = g_xhi + (size_t)rowBase * 128;
#pragma unroll
        for (int q = 0; q < 8; q++) {
            int i = tid + 256 * q;
            int r = i >> 4, c = i & 15;
            uint32_t off = r * 256 + ((c ^ (r & 7)) << 4);
            cp_async16(sbase + TD_AH + off, s2 + i * 8);
        }
    }
    {
#pragma unroll
        for (int q = 0; q < 4; q++) {
            int i = tid + 256 * q;
            int r = i >> 4, c = i & 15;
            uint32_t off = r * 256 + ((c ^ (r & 7)) << 4);
            cp_async16(sbase + TD_BH + off, g_Td_hi + i * 8);
        }
    }
    CP_COMMIT();
    CP_WAIT(0);
    __syncthreads();

    float acc[8][4];
#pragma unroll
    for (int n = 0; n < 8; n++)
#pragma unroll
        for (int e = 0; e < 4; e++) acc[n][e] = 0.f;

    const int a_r = wid * 16 + (lane & 15);
    const int a_kh = lane >> 4;
    const int b_grp = lane >> 3;
    const int b_nt_off = b_grp >> 1;
    const int b_kh = b_grp & 1;
    const int b_nl = lane & 7;

    for (int ks = 0; ks < 8; ks++) {
        uint32_t ach = (uint32_t)(((ks * 2 + a_kh) ^ (a_r & 7)) << 4) + a_r * 256;
        uint32_t ah0, ah1, ah2, ah3;
        ldsm_x4(ah0, ah1, ah2, ah3, sbase + TD_AH + ach);
#pragma unroll
        for (int nt2 = 0; nt2 < 8; nt2 += 2) {
            int n = (nt2 + b_nt_off) * 8 + b_nl;
            uint32_t boff = (uint32_t)n * 256 + (uint32_t)(((ks * 2 + b_kh) ^ (n & 7)) << 4);
            uint32_t bh0, bh1, bh2, bh3;
            ldsm_x4(bh0, bh1, bh2, bh3, sbase + TD_BH + boff);
            mma16816(acc[nt2], ah0, ah1, ah2, ah3, bh0, bh1);
            mma16816(acc[nt2 + 1], ah0, ah1, ah2, ah3, bh2, bh3);
        }
    }
    int tq = lane >> 2, tr = lane & 3;
#pragma unroll
    for (int nt = 0; nt < 8; nt++) {
        int j = nt * 8 + tr * 2;
#pragma unroll
        for (int h = 0; h < 2; h++) {
            int m = rowBase + wid * 16 + tq + h * 8;
            *(float2*)&g_ggnn[(size_t)m * DCC + j] =
                make_float2(acc[nt][2 * h], acc[nt][2 * h + 1]);
        }
    }
}

// ---------------- attention (collapsed node weights) --------------------------
__global__ void attn_kernel(const float* __restrict__ c_id,
                            const float* __restrict__ c_embed,
                            const float* __restrict__ concept_embedding) {
    extern __shared__ float smf[];
    float* shg = smf;
    float* pbuf = shg + NNODE * 65;
    float* qbuf = pbuf + 8 * NNODE;
    float* wnode = qbuf + 8 * 64;
    float* accd = wnode + NNODE;
    float* snum = accd + 64;
    int g = blockIdx.x;
    int tid = threadIdx.x;
    for (int i = tid; i < NNODE * DCC; i += 256) {
        int n = i >> 6, d = i & 63;
        shg[n * 65 + d] = g_ggnn[(size_t)(g * NNODE + n) * DCC + d];
    }
    for (int i = tid; i < NNODE; i += 256) wnode[i] = 0.f;
    if (tid < 64) accd[tid] = 0.f;
    if (tid == 0) snum[0] = 0.f;
    __syncthreads();
    if (tid < CP1N) atomicAdd(snum, c_id[g * CP1N + tid]);
    __syncthreads();
    int warp = tid >> 5, lane = tid & 31;
    for (int c = warp; c < CP1N; c += 8) {
        float ce = c_embed[g * CP1N + c];
        if (ce == 0.f) continue;
        qbuf[warp * 64 + lane] = ce * concept_embedding[c * DCC + lane];
        qbuf[warp * 64 + lane + 32] = ce * concept_embedding[c * DCC + lane + 32];
        __syncwarp();
        float mx = -1e30f;
        for (int n = lane; n < NNODE; n += 32) {
            float s = 0.f;
#pragma unroll 16
            for (int d = 0; d < DCC; d++) s += qbuf[warp * 64 + d] * shg[n * 65 + d];
            pbuf[warp * NNODE + n] = s;
            mx = fmaxf(mx, s);
        }
#pragma unroll
        for (int o = 16; o > 0; o >>= 1) mx = fmaxf(mx, __shfl_xor_sync(0xffffffffu, mx, o));
        float ssum = 0.f;
        for (int n = lane; n < NNODE; n += 32) {
            float p = expf(pbuf[warp * NNODE + n] - mx);
            pbuf[warp * NNODE + n] = p;
            ssum += p;
        }
#pragma unroll
        for (int o = 16; o > 0; o >>= 1) ssum += __shfl_xor_sync(0xffffffffu, ssum, o);
        float inv = ce / ssum;
        for (int n = lane; n < NNODE; n += 32)
            atomicAdd(&wnode[n], inv * pbuf[warp * NNODE + n]);
    }
    __syncthreads();
    {
        int d = tid & 63, q = tid >> 6;
        float partial = 0.f;
        for (int n = q * 50; n < q * 50 + 50; n++)
            partial += wnode[n] * shg[n * 65 + d];
        atomicAdd(&accd[d], partial);
    }
    __syncthreads();
    if (tid < DCC) {
        float nv = snum[0];
        if (nv == 0.f) nv = 1.f;
        g_attn[g * DCC + tid] = accd[tid] / nv;
    }
}

// ---------------- LSTM input GEMM: 8 sequences per block ---------------------
__global__ void lstm_pre_kernel(const float* __restrict__ c_embed,
                                const float* __restrict__ cur_result,
                                const float* __restrict__ lstm_b_ih) {
    __shared__ float xin[8][FEATN];
    int s0 = blockIdx.x * 8;
    int tid = threadIdx.x;
    for (int i = tid; i < 8 * FEATN; i += 256) {
        int si = i / FEATN, f = i % FEATN;
        int s = s0 + si;
        float v;
        if (f < CP1N) v = c_embed[(size_t)s * CP1N + f];
        else if (f < CP1N + DCC) v = g_attn[(size_t)s * DCC + (f - CP1N)];
        else v = cur_result[(size_t)s * 2 + (f - CP1N - DCC)];
        xin[si][f] = v;
    }
    __syncthreads();
    int m = blockIdx.y * 256 + tid;
    int q = m & 3, j = m >> 2;
    float b = lstm_b_ih[q * 256 + j];
    float a0 = b, a1 = b, a2 = b, a3 = b, a4 = b, a5 = b, a6 = b, a7 = b;
    for (int k = 0; k < FEATN; k++) {
        float w = g_LihT[(size_t)k * 1024 + m];
        a0 += xin[0][k] * w; a1 += xin[1][k] * w;
        a2 += xin[2][k] * w; a3 += xin[3][k] * w;
        a4 += xin[4][k] * w; a5 += xin[5][k] * w;
        a6 += xin[6][k] * w; a7 += xin[7][k] * w;
    }
    g_pre[(size_t)(s0 + 0) * 1024 + m] = a0;
    g_pre[(size_t)(s0 + 1) * 1024 + m] = a1;
    g_pre[(size_t)(s0 + 2) * 1024 + m] = a2;
    g_pre[(size_t)(s0 + 3) * 1024 + m] = a3;
    g_pre[(size_t)(s0 + 4) * 1024 + m] = a4;
    g_pre[(size_t)(s0 + 5) * 1024 + m] = a5;
    g_pre[(size_t)(s0 + 6) * 1024 + m] = a6;
    g_pre[(size_t)(s0 + 7) * 1024 + m] = a7;
}

// LSTM recurrence: cluster of 8 CTAs per batch; bf16-packed weights in smem,
// double-buffered h, ONE cluster barrier per step.
__global__ void __cluster_dims__(8, 1, 1) __launch_bounds__(128, 1)
lstm_rec_kernel(const float* __restrict__ b_hh) {
    extern __shared__ __align__(16) char smlc[];
    __nv_bfloat162* sWb = (__nv_bfloat162*)smlc;          // 128 k2 x 128 tid
    float* sh = (float*)(smlc + 128 * 128 * 4);           // 2 x 256
    int tid = threadIdx.x;
    int r = blockIdx.x & 7;
    int b = blockIdx.x >> 3;
    for (int i = tid; i < 128 * 128; i += 128)
        sWb[i] = g_WhhB[(size_t)(i >> 7) * 1024 + r * 128 + (i & 127)];
    for (int i = tid; i < 512; i += 128) sh[i] = 0.f;
    int q = tid & 3, jl = tid >> 2;
    int jg = r * 32 + jl;
    float bias = b_hh[q * 256 + jg];
    float c = 0.f;
    uint32_t sh_my0 = smem_u32(&sh[jg]);
    uint32_t sh_my1 = smem_u32(&sh[256 + jg]);
    __syncthreads();
    CLUSTER_BAR();
    int lbase = (tid & 31) & ~3;
    for (int t = 0; t < SLEN; t++) {
        int s = b * SLEN + t;
        const float* shc = sh + 256 * (t & 1);
        uint32_t sh_next = (t & 1) ? sh_my0 : sh_my1;
        float acc = g_pre[(size_t)s * 1024 + r * 128 + tid] + bias;
#pragma unroll 8
        for (int k2 = 0; k2 < 128; k2++) {
            float2 h2 = *(const float2*)&shc[2 * k2];
            float2 wf = __bfloat1622float2(sWb[k2 * 128 + tid]);
            acc = fmaf(h2.x, wf.x, acc);
            acc = fmaf(h2.y, wf.y, acc);
        }
        float vi = __shfl_sync(0xffffffffu, acc, lbase + 0);
        float vf = __shfl_sync(0xffffffffu, acc, lbase + 1);
        float vg = __shfl_sync(0xffffffffu, acc, lbase + 2);
        float vo = __shfl_sync(0xffffffffu, acc, lbase + 3);
        if (q == 0) {
            c = sigmoid_fast(vf) * c + sigmoid_fast(vi) * tanh_fast(vg);
            float h = sigmoid_fast(vo) * tanh_fast(c);
            g_hout[(size_t)s * HHID + jg] = h;
#pragma unroll
            for (int dst = 0; dst < 8; dst++) {
                uint32_t rem;
                asm("mapa.shared::cluster.u32 %0, %1, %2;" : "=r"(rem)
                    : "r"(sh_next), "r"(dst));
                asm volatile("st.shared::cluster.f32 [%0], %1;" :: "r"(rem), "f"(h)
                             : "memory");
            }
        }
        CLUSTER_BAR();
    }
}

// ---------------- pred + BCE + final -----------------------------------------
__global__ void pred_kernel(const float* __restrict__ target_c,
                            const float* __restrict__ result,
                            const float* __restrict__ pred_w,
                            const float* __restrict__ pred_b) {
    __shared__ float sh[HHID];
    __shared__ float s_p, s_n;
    int i = blockIdx.x, tid = threadIdx.x;
    sh[tid] = g_hout[(size_t)i * HHID + tid];
    sh[tid + 128] = g_hout[(size_t)i * HHID + tid + 128];
    if (tid == 0) { s_p = 0.f; s_n = 0.f; }
    __syncthreads();
    int warp = tid >> 5, lane = tid & 31;
    float lp = 0.f, ln = 0.f;
    for (int c = warp; c < CP1N; c += 4) {
        float tc = target_c[i * CP1N + c];
        if (tc != 0.f) {
            float s = 0.f;
            for (int d = lane; d < HHID; d += 32) s += pred_w[c * HHID + d] * sh[d];
#pragma unroll
            for (int o = 16; o > 0; o >>= 1) s += __shfl_xor_sync(0xffffffffu, s, o);
            if (lane == 0) { lp += tc * (s + pred_b[c]); ln += tc; }
        }
    }
    if (lane == 0) { atomicAdd(&s_p, lp); atomicAdd(&s_n, ln); }
    __syncthreads();
    if (tid == 0) {
        float nc = s_n;
        int mask = nc > 0.f;
        float fp = s_p / (mask ? nc : 1.f);
        float ft = result[i];
        float bce = fmaxf(fp, 0.f) - fp * ft + log1pf(expf(-fabsf(fp)));
        g_fp[i] = fp;
        g_mf[i] = mask ? 1.f : 0.f;
        g_bce[i] = mask ? bce : 0.f;
    }
}

__global__ void final_kernel(const float* __restrict__ result, float* __restrict__ out,
                             int out_size) {
    __shared__ float rb[256], rm[256];
    int tid = threadIdx.x;
    float sb = 0.f, smm = 0.f;
    for (int i = tid; i < GG; i += 256) { sb += g_bce[i]; smm += g_mf[i]; }
    rb[tid] = sb; rm[tid] = smm;
    __syncthreads();
    for (int o = 128; o > 0; o >>= 1) {
        if (tid < o) { rb[tid] += rb[tid + o]; rm[tid] += rm[tid + o]; }
        __syncthreads();
    }
    if (tid == 0 && out_size > 0) out[0] = rb[0] / fmaxf(rm[0], 1.f);
    for (int i = tid; i < GG; i += 256) {
        if (1 + i < out_size) out[1 + i] = 1.f / (1.f + expf(-g_fp[i]));
        if (1 + GG + i < out_size) out[1 + GG + i] = result[i];
    }
}

// ---------------- launcher ---------------------------------------------------
extern "C" void kernel_launch(void* const* d_in, const int* in_sizes, int n_in,
                              void* d_out, int out_size) {
    const float* c_id       = (const float*)d_in[1];
    const int*   node_id    = (const int*)d_in[2];
    const int*   edge       = (const int*)d_in[3];
    const int*   edge_type  = (const int*)d_in[4];
    const float* target_c   = (const float*)d_in[5];
    const float* result     = (const float*)d_in[6];
    const float* c_embed    = (const float*)d_in[7];
    const float* cur_result = (const float*)d_in[8];
    const float* node_embed_w = (const float*)d_in[9];
    const float* edge_embed_w = (const float*)d_in[10];
    const float* ggnn_w     = (const float*)d_in[11];
    const float* gru_w_ih   = (const float*)d_in[12];
    const float* gru_w_hh   = (const float*)d_in[13];
    const float* gru_b_ih   = (const float*)d_in[14];
    const float* gru_b_hh   = (const float*)d_in[15];
    const float* transdim_w = (const float*)d_in[16];
    const float* concept_embedding = (const float*)d_in[17];
    const float* lstm_w_ih  = (const float*)d_in[18];
    const float* lstm_w_hh  = (const float*)d_in[19];
    const float* lstm_b_ih  = (const float*)d_in[20];
    const float* lstm_b_hh  = (const float*)d_in[21];
    const float* pred_w     = (const float*)d_in[22];
    const float* pred_b     = (const float*)d_in[23];
    float* out = (float*)d_out;
    (void)in_sizes; (void)n_in;

    const int SCAT_SMEM = NNODE * DD * 2;                  // 51200
    const int LSTM_SMEM = 128 * 128 * 4 + 512 * 4;         // 67584
    const int ATTN_SMEM = (NNODE * 65 + 8 * NNODE + 8 * 64 + NNODE + 64 + 4) * 4;
    cudaFuncSetAttribute(layer_mma, cudaFuncAttributeMaxDynamicSharedMemorySize, SM_TOT);
    cudaFuncSetAttribute(gemm_td, cudaFuncAttributeMaxDynamicSharedMemorySize, TD_TOT);
    cudaFuncSetAttribute(attn_kernel, cudaFuncAttributeMaxDynamicSharedMemorySize, ATTN_SMEM);
    cudaFuncSetAttribute(scatter_csr, cudaFuncAttributeMaxDynamicSharedMemorySize, SCAT_SMEM);
    cudaFuncSetAttribute(lstm_rec_kernel, cudaFuncAttributeMaxDynamicSharedMemorySize,
                         LSTM_SMEM);

    prep_kernel<<<1500, 256>>>(edge_embed_w, gru_w_hh, transdim_w, lstm_w_ih, lstm_w_hh);
    comb_kernel<<<(4 * 384 * 128 + 255) / 256, 256>>>(ggnn_w, gru_w_ih);
    gather_kernel<<<GN / 8, 256>>>(node_id, node_embed_w);
    csr_build<<<GG, 256>>>(edge, edge_type);

    for (int l = 0; l < 4; l++) {
        scatter_csr<<<GG, 512, SCAT_SMEM>>>(0);
        layer_mma<<<GN / 64, 256, SM_TOT>>>(l, gru_b_ih, gru_b_hh);
    }

    gemm_td<<<GN / 128, 256, TD_TOT>>>();
    attn_kernel<<<GG, 256, ATTN_SMEM>>>(c_id, c_embed, concept_embedding);
    lstm_pre_kernel<<<dim3(GG / 8, 4), 256>>>(c_embed, cur_result, lstm_b_ih);
    lstm_rec_kernel<<<BSZ * 8, 128, LSTM_SMEM>>>(lstm_b_hh);
    pred_kernel<<<GG, 128>>>(target_c, result, pred_w, pred_b);
    final_kernel<<<1, 256>>>(result, out, out_size);
}